// round 9
// baseline (speedup 1.0000x reference)
#include <cuda_runtime.h>
#include <cuda_fp16.h>
#include <math.h>
#include <stdint.h>

#define B_   1024
#define S_   50
#define E_   300
#define H_   200
#define M_   51200
#define NGX  1200          // stacked f|b gate width
#define KP_GX   320        // K=300 padded
#define KP_SENT 416        // K=400 padded
#define NP_GX   1280
#define NP_SENT 256
#define GRU_ROWS 14
#define NOV_ROWS 7

// ---------------- scratch (device globals; no allocations) ----------------
__device__ __align__(256) __half g_Ahi[(size_t)M_ * KP_GX];
__device__ __align__(256) __half g_Alo[(size_t)M_ * KP_GX];
__device__ __align__(256) __half g_Hhi[(size_t)M_ * KP_SENT];   // pad cols stay 0
__device__ __align__(256) __half g_Hlo[(size_t)M_ * KP_SENT];
__device__ __align__(256) __half g_Bgx[(size_t)NP_GX * KP_GX];
__device__ __align__(256) __half g_Bse[(size_t)NP_SENT * KP_SENT];
__device__ float g_gx[(size_t)M_ * NGX];
__device__ float g_sent[(size_t)M_ * H_];
__device__ float g_avg[B_ * H_];
__device__ float g_tmp[B_ * H_];
__device__ float g_doc[B_ * H_];
__device__ float g_Wqf[H_ * 3 * H_];
__device__ float g_Wqb[H_ * 3 * H_];
__device__ float g_Wnq[H_ * H_];

// ---------------- helpers ----------------
__device__ __forceinline__ uint32_t smem_u32(const void* p) {
    uint32_t a;
    asm("{ .reg .u64 t; cvta.to.shared.u64 t, %1; cvt.u32.u64 %0, t; }" : "=r"(a) : "l"(p));
    return a;
}
__device__ __forceinline__ void ldm4(uint32_t* r, uint32_t addr) {
    asm volatile("ldmatrix.sync.aligned.m8n8.x4.shared.b16 {%0,%1,%2,%3}, [%4];"
        : "=r"(r[0]), "=r"(r[1]), "=r"(r[2]), "=r"(r[3]) : "r"(addr));
}
__device__ __forceinline__ void mma_f16(float* c, const uint32_t* a, const uint32_t* b) {
    asm volatile(
        "mma.sync.aligned.m16n8k16.row.col.f32.f16.f16.f32 "
        "{%0,%1,%2,%3}, {%4,%5,%6,%7}, {%8,%9}, {%0,%1,%2,%3};"
        : "+f"(c[0]), "+f"(c[1]), "+f"(c[2]), "+f"(c[3])
        : "r"(a[0]), "r"(a[1]), "r"(a[2]), "r"(a[3]), "r"(b[0]), "r"(b[1]));
}
__device__ __forceinline__ float2 ffma2(float2 a, float2 b, float2 c) {
    unsigned long long ua = *(unsigned long long*)&a;
    unsigned long long ub = *(unsigned long long*)&b;
    unsigned long long uc = *(unsigned long long*)&c;
    unsigned long long r;
    asm("fma.rn.f32x2 %0, %1, %2, %3;" : "=l"(r) : "l"(ua), "l"(ub), "l"(uc));
    return *(float2*)&r;
}

// ---------------- combined weight pack for scans (one launch) ----------------
// job layout: [0, 30000): wqf (G=600), [30000, 60000): wqb, [60000, 70000): wnq (G=200)
__global__ void pack_all(const float* __restrict__ Whh_f, const float* __restrict__ Whh_b,
                         const float* __restrict__ Wnov,
                         float4* __restrict__ wqf, float4* __restrict__ wqb,
                         float4* __restrict__ wnq) {
    int i = blockIdx.x * blockDim.x + threadIdx.x;
    const float* src;
    float4* dst;
    int G, idx;
    if (i < 30000)      { src = Whh_f; dst = wqf; G = 600; idx = i; }
    else if (i < 60000) { src = Whh_b; dst = wqb; G = 600; idx = i - 30000; }
    else if (i < 70000) { src = Wnov;  dst = wnq; G = 200; idx = i - 60000; }
    else return;
    int k4 = idx / G, g = idx % G;
    const float* s = src + (size_t)g * 200 + 4 * k4;
    dst[idx] = make_float4(s[0], s[1], s[2], s[3]);
}

// ---------------- combined gx-side fp16 conversion (one launch) ----------------
// blocks [0, 1600): Bgx weights (Wih_f|Wih_b stacked, no lo)
// blocks [1600, 65600): seq hi/lo
__global__ void conv_prep(const float* __restrict__ Wih_f, const float* __restrict__ Wih_b,
                          const float* __restrict__ seq,
                          __half* __restrict__ Bgx,
                          __half* __restrict__ Ahi, __half* __restrict__ Alo) {
    if (blockIdx.x < 1600) {
        int i = blockIdx.x * 256 + threadIdx.x;
        if (i >= NP_GX * KP_GX) return;
        int row = i / KP_GX, k = i - row * KP_GX;
        float x = 0.f;
        if (k < E_) {
            if (row < 600) x = Wih_f[(size_t)row * E_ + k];
            else if (row < 1200) x = Wih_b[(size_t)(row - 600) * E_ + k];
        }
        Bgx[i] = __float2half_rn(x);
    } else {
        size_t i = (size_t)(blockIdx.x - 1600) * 256 + threadIdx.x;
        if (i >= (size_t)M_ * KP_GX) return;
        int row = (int)(i / KP_GX), k = (int)(i - (size_t)row * KP_GX);
        float x = (k < E_) ? seq[(size_t)row * E_ + k] : 0.f;
        __half h = __float2half_rn(x);
        Ahi[i] = h;
        Alo[i] = __float2half_rn(x - __half2float(h));
    }
}

// ---------------- generic fp32 -> fp16 conversion (sent weights) ----------------
__global__ void conv_f16(const float* __restrict__ X0,
                         int rows0, int K, int Kpad, int totalRows,
                         __half* __restrict__ hi) {
    int i = blockIdx.x * blockDim.x + threadIdx.x;
    if (i >= totalRows * Kpad) return;
    int row = i / Kpad, k = i - row * Kpad;
    float x = (k < K && row < rows0) ? X0[(size_t)row * K + k] : 0.f;
    hi[i] = __float2half_rn(x);
}

// ---------------- 2-pass split-fp16 tensor-core GEMM (mma.sync) ----------------
#define NSTAGE 3
#define STAGE_BYTES 30720
#define MMA_SMEM (NSTAGE * STAGE_BYTES)

template <int ACT>
__global__ void __launch_bounds__(256, 2)
mma_gemm(const __half* __restrict__ Ahi, const __half* __restrict__ Alo,
         const __half* __restrict__ Bm,
         const float* __restrict__ bias0, const float* __restrict__ bias1, int nsplit,
         float* __restrict__ C, int ldc, int Nvalid, int Kpad) {
    extern __shared__ __align__(16) __half smbuf[];
    uint32_t sb = smem_u32(smbuf);
    int tid = threadIdx.x;
    int w = tid >> 5, lane = tid & 31;
    int wm = (w >> 1) * 32, wn = (w & 1) * 64;
    int m0 = blockIdx.y * 128, n0 = blockIdx.x * 128;

    const __half* gsrc0 = Ahi + (size_t)m0 * Kpad;
    const __half* gsrc1 = Alo + (size_t)m0 * Kpad;
    const __half* gsrc2 = Bm + (size_t)n0 * Kpad;

    float acc[2][8][4];
#pragma unroll
    for (int i = 0; i < 2; i++)
#pragma unroll
        for (int j = 0; j < 8; j++)
#pragma unroll
            for (int e = 0; e < 4; e++) acc[i][j][e] = 0.f;

    int rowA = ((lane >> 3) & 1) * 8 + (lane & 7);
    int kA   = ((lane >> 4) & 1) * 8;
    int rowB = ((lane >> 4) & 1) * 8 + (lane & 7);
    int kB   = ((lane >> 3) & 1) * 8;

    int nst = Kpad / 32;
    auto load_stage = [&](int s) {
        int buf = s % NSTAGE;
        int k0 = s * 32;
#pragma unroll
        for (int i = 0; i < 6; i++) {
            int t = tid + i * 256;
            int mat = t >> 9;
            int c = t & 511;
            int row = c >> 2, kc = c & 3;
            uint32_t dst = sb + buf * STAGE_BYTES + mat * 10240 + row * 80 + kc * 16;
            const __half* src =
                (mat == 0 ? gsrc0 : mat == 1 ? gsrc1 : gsrc2)
                + (size_t)row * Kpad + k0 + kc * 8;
            asm volatile("cp.async.cg.shared.global [%0], [%1], 16;" :: "r"(dst), "l"(src));
        }
        asm volatile("cp.async.commit_group;");
    };

    load_stage(0);
    if (nst > 1) load_stage(1);
    for (int s = 0; s < nst; s++) {
        if (s + 2 < nst) {
            load_stage(s + 2);
            asm volatile("cp.async.wait_group 2;");
        } else if (s + 1 < nst) {
            asm volatile("cp.async.wait_group 1;");
        } else {
            asm volatile("cp.async.wait_group 0;");
        }
        __syncthreads();
        uint32_t base = sb + (s % NSTAGE) * STAGE_BYTES;
#pragma unroll
        for (int k16 = 0; k16 < 32; k16 += 16) {
            uint32_t ah[2][4], al[2][4];
#pragma unroll
            for (int ma = 0; ma < 2; ma++) {
                uint32_t off = (uint32_t)(((wm + ma * 16 + rowA) * 40 + k16 + kA) * 2);
                ldm4(ah[ma], base + off);
                ldm4(al[ma], base + 10240 + off);
            }
            uint32_t bh[4][4];
#pragma unroll
            for (int nb = 0; nb < 4; nb++) {
                uint32_t off = (uint32_t)(((wn + nb * 16 + rowB) * 40 + k16 + kB) * 2);
                ldm4(bh[nb], base + 20480 + off);
            }
#pragma unroll
            for (int ma = 0; ma < 2; ma++)
#pragma unroll
                for (int na = 0; na < 8; na++)
                    mma_f16(acc[ma][na], ah[ma], &bh[na >> 1][(na & 1) * 2]);
#pragma unroll
            for (int ma = 0; ma < 2; ma++)
#pragma unroll
                for (int na = 0; na < 8; na++)
                    mma_f16(acc[ma][na], al[ma], &bh[na >> 1][(na & 1) * 2]);
        }
        __syncthreads();
    }

    int r0 = m0 + wm + (lane >> 2);
    int cb = n0 + wn + (lane & 3) * 2;
#pragma unroll
    for (int ma = 0; ma < 2; ma++) {
        int r = r0 + ma * 16;
#pragma unroll
        for (int na = 0; na < 8; na++) {
            int col = cb + na * 8;
            if (col < Nvalid) {
                float b0v = (col < nsplit) ? bias0[col] : bias1[col - nsplit];
                float b1v = (col + 1 < nsplit) ? bias0[col + 1] : bias1[col + 1 - nsplit];
                float2 v0 = make_float2(acc[ma][na][0] + b0v, acc[ma][na][1] + b1v);
                float2 v1 = make_float2(acc[ma][na][2] + b0v, acc[ma][na][3] + b1v);
                if (ACT == 1) {
                    v0.x = fmaxf(v0.x, 0.f); v0.y = fmaxf(v0.y, 0.f);
                    v1.x = fmaxf(v1.x, 0.f); v1.y = fmaxf(v1.y, 0.f);
                }
                *(float2*)&C[(size_t)r * ldc + col] = v0;
                *(float2*)&C[(size_t)(r + 8) * ldc + col] = v1;
            }
        }
    }
}

// ---------------- small fp32 SGEMM (doc MLP only) ----------------
template <int ACT>
__global__ void __launch_bounds__(256, 2)
sgemm_nt(const float* __restrict__ A, const float* __restrict__ Bm,
         const float* __restrict__ bias, float* __restrict__ C,
         int M, int N, int K) {
    __shared__ float As[2][8][128];
    __shared__ float Bs[2][8][128];
    int tid = threadIdx.x;
    int tx = tid & 15, ty = tid >> 4;
    int m0 = blockIdx.y * 128, n0 = blockIdx.x * 128;
    int lr = tid >> 1, lq = tid & 1;
    int m = m0 + lr, n = n0 + lr;
    bool nok = (n < N);
    const float* Arow = A + (size_t)m * K;
    const float* Brow = Bm + (size_t)n * K;
    float2 acc[8][4];
#pragma unroll
    for (int i = 0; i < 8; i++)
#pragma unroll
        for (int j = 0; j < 4; j++) acc[i][j] = make_float2(0.f, 0.f);
    float av[4], bv[4];
    auto load_chunk = [&](int k0) {
        int k = k0 + lq * 4;
#pragma unroll
        for (int i = 0; i < 4; i++) {
            av[i] = (k + i < K) ? Arow[k + i] : 0.f;
            bv[i] = (nok && k + i < K) ? Brow[k + i] : 0.f;
        }
    };
    auto store_chunk = [&](int buf) {
#pragma unroll
        for (int i = 0; i < 4; i++) {
            As[buf][lq * 4 + i][lr] = av[i];
            Bs[buf][lq * 4 + i][lr] = bv[i];
        }
    };
    auto compute = [&](int buf) {
#pragma unroll
        for (int kk = 0; kk < 8; kk++) {
            float4 a0 = *(const float4*)&As[buf][kk][ty * 8];
            float4 a1 = *(const float4*)&As[buf][kk][ty * 8 + 4];
            float4 b0 = *(const float4*)&Bs[buf][kk][tx * 8];
            float4 b1 = *(const float4*)&Bs[buf][kk][tx * 8 + 4];
            float a[8] = {a0.x, a0.y, a0.z, a0.w, a1.x, a1.y, a1.z, a1.w};
            float2 b2[4] = {make_float2(b0.x, b0.y), make_float2(b0.z, b0.w),
                            make_float2(b1.x, b1.y), make_float2(b1.z, b1.w)};
#pragma unroll
            for (int i = 0; i < 8; i++) {
                float2 ad = make_float2(a[i], a[i]);
#pragma unroll
                for (int j = 0; j < 4; j++) acc[i][j] = ffma2(ad, b2[j], acc[i][j]);
            }
        }
    };
    int nt = (K + 7) / 8;
    load_chunk(0);
    store_chunk(0);
    __syncthreads();
    int cur = 0;
    for (int t = 1; t < nt; t++) {
        load_chunk(t * 8);
        compute(cur);
        store_chunk(cur ^ 1);
        __syncthreads();
        cur ^= 1;
    }
    compute(cur);
#pragma unroll
    for (int i = 0; i < 8; i++) {
        int mm = m0 + ty * 8 + i;
#pragma unroll
        for (int j = 0; j < 4; j++) {
            int nn = n0 + tx * 8 + j * 2;
            if (nn + 1 < N) {
                float2 v = acc[i][j];
                if (bias) { v.x += bias[nn]; v.y += bias[nn + 1]; }
                if (ACT == 1) { v.x = fmaxf(v.x, 0.f); v.y = fmaxf(v.y, 0.f); }
                if (ACT == 2) { v.x = tanhf(v.x); v.y = tanhf(v.y); }
                *(float2*)&C[(size_t)mm * N + nn] = v;
            } else if (nn < N) {
                float v = acc[i][j].x + (bias ? bias[nn] : 0.f);
                if (ACT == 1) v = fmaxf(v, 0.f);
                if (ACT == 2) v = tanhf(v);
                C[(size_t)mm * N + nn] = v;
            }
        }
    }
}

// ---------------- bidirectional GRU recurrence (persistent, 148 blocks) --------
// Register-double-buffered weight prefetch hides L2 latency on Wq loads.
__global__ void __launch_bounds__(608, 1)
gru_kernel(const float* __restrict__ gx,
           const float4* __restrict__ Wqf, const float4* __restrict__ Wqb,
           const float* __restrict__ bhhf, const float* __restrict__ bhhb,
           __half* __restrict__ Hhi, __half* __restrict__ Hlo) {
    extern __shared__ float sm[];
    float* hs  = sm;                      // [GRU_ROWS][200]
    float* ghs = sm + GRU_ROWS * 200;     // [GRU_ROWS][600]
    int dir = blockIdx.y;
    const float4* Wq = dir ? Wqb : Wqf;
    const float* bhh = dir ? bhhb : bhhf;
    int b0 = blockIdx.x * GRU_ROWS;
    int tid = threadIdx.x;

    for (int i = tid; i < GRU_ROWS * 200; i += blockDim.x) hs[i] = 0.f;
    __syncthreads();

    for (int t = 0; t < S_; t++) {
        int s = dir ? (S_ - 1 - t) : t;
        if (tid < 600) {
            float2 acc2[GRU_ROWS];
#pragma unroll
            for (int r = 0; r < GRU_ROWS; r++) acc2[r] = make_float2(0.f, 0.f);
            float4 w = Wq[tid];
#pragma unroll 2
            for (int k4 = 0; k4 < 50; k4++) {
                float4 wn = Wq[(k4 < 49 ? k4 + 1 : k4) * 600 + tid];  // prefetch
                float2 w01 = make_float2(w.x, w.y);
                float2 w23 = make_float2(w.z, w.w);
#pragma unroll
                for (int r = 0; r < GRU_ROWS; r++) {
                    float4 h4 = *(const float4*)&hs[r * 200 + k4 * 4];
                    acc2[r] = ffma2(w01, make_float2(h4.x, h4.y), acc2[r]);
                    acc2[r] = ffma2(w23, make_float2(h4.z, h4.w), acc2[r]);
                }
                w = wn;
            }
            float bb = bhh[tid];
#pragma unroll
            for (int r = 0; r < GRU_ROWS; r++) ghs[r * 600 + tid] = acc2[r].x + acc2[r].y + bb;
        }
        __syncthreads();
        for (int idx = tid; idx < GRU_ROWS * 200; idx += blockDim.x) {
            int r = idx / 200, j = idx % 200;
            int b = b0 + r;
            int bc = b < B_ ? b : B_ - 1;
            const float* gxr = gx + (size_t)(bc * S_ + s) * NGX + dir * 600;
            float gr = ghs[r * 600 + j];
            float gz = ghs[r * 600 + 200 + j];
            float gn = ghs[r * 600 + 400 + j];
            float rg = 1.f / (1.f + __expf(-(gxr[j] + gr)));
            float zg = 1.f / (1.f + __expf(-(gxr[200 + j] + gz)));
            float nn = tanhf(gxr[400 + j] + rg * gn);
            float hprev = hs[r * 200 + j];
            float hnew = (1.f - zg) * nn + zg * hprev;
            hs[r * 200 + j] = hnew;
            if (b < B_) {
                size_t o = (size_t)(b * S_ + s) * KP_SENT + dir * 200 + j;
                __half hb = __float2half_rn(hnew);
                Hhi[o] = hb;
                Hlo[o] = __float2half_rn(hnew - __half2float(hb));
            }
        }
        __syncthreads();
    }
}

// ---------------- avg over sequence ----------------
__global__ void avg_kernel(const float* __restrict__ sent, const int* __restrict__ length,
                           float* __restrict__ avg) {
    int i = blockIdx.x * blockDim.x + threadIdx.x;
    if (i < B_ * H_) {
        int b = i / H_, h = i % H_;
        float s = 0.f;
        for (int t = 0; t < S_; t++) s += sent[((size_t)(b * S_ + t)) * H_ + h];
        avg[i] = s / (float)length[b];
    }
}

// ---------------- novelty scan + fused base logits (148 blocks x 7 rows) -------
__global__ void __launch_bounds__(256, 1)
nov_kernel(const float* __restrict__ sent, const float4* __restrict__ Wnq,
           const float* __restrict__ bnov,
           const float* __restrict__ wcont, const float* __restrict__ doc,
           const int* __restrict__ apos, const int* __restrict__ rpos,
           const float* __restrict__ apos_table, const float* __restrict__ rpos_table,
           const float* __restrict__ apos_w, const float* __restrict__ rpos_w,
           const float* __restrict__ apos_b, const float* __restrict__ rpos_b,
           const float* __restrict__ bcont, const float* __restrict__ bias,
           float* __restrict__ out) {
    __shared__ float sum_s[NOV_ROWS * 200];
    __shared__ float st[NOV_ROWS * 200];
    __shared__ float ps[NOV_ROWS * 200];
    __shared__ float wd[NOV_ROWS * 200];
    __shared__ float gsig[8];
    __shared__ float s_scal;
    int tid = threadIdx.x;
    int b0 = blockIdx.x * NOV_ROWS;
    if (tid == 0) s_scal = *bcont + *apos_b + *rpos_b + *bias;
    for (int i = tid; i < NOV_ROWS * 200; i += 256) {
        int r = i / 200, j = i % 200;
        int b = b0 + r; if (b >= B_) b = B_ - 1;
        sum_s[i] = 0.f;
        wd[i] = wcont[j] + doc[(size_t)b * 200 + j];
    }
    __syncthreads();
    for (int t = 0; t < S_; t++) {
        for (int i = tid; i < NOV_ROWS * 200; i += 256) {
            int r = i / 200, j = i % 200;
            int b = b0 + r; if (b >= B_) b = B_ - 1;
            st[i] = sent[((size_t)(b * S_ + t)) * 200 + j];
        }
        __syncthreads();
        if (tid < 200) {
            float2 acc2[NOV_ROWS];
#pragma unroll
            for (int r = 0; r < NOV_ROWS; r++) acc2[r] = make_float2(0.f, 0.f);
            float4 w = Wnq[tid];
#pragma unroll 2
            for (int k4 = 0; k4 < 50; k4++) {
                float4 wn = Wnq[(k4 < 49 ? k4 + 1 : k4) * 200 + tid];  // prefetch
                float2 w01 = make_float2(w.x, w.y);
                float2 w23 = make_float2(w.z, w.w);
#pragma unroll
                for (int r = 0; r < NOV_ROWS; r++) {
                    float4 h4 = *(const float4*)&st[r * 200 + k4 * 4];
                    acc2[r] = ffma2(w01, make_float2(h4.x, h4.y), acc2[r]);
                    acc2[r] = ffma2(w23, make_float2(h4.z, h4.w), acc2[r]);
                }
                w = wn;
            }
            float bb = bnov[tid];
#pragma unroll
            for (int r = 0; r < NOV_ROWS; r++)
                ps[r * 200 + tid] = (acc2[r].x + acc2[r].y + bb) * tanhf(sum_s[r * 200 + tid]);
        }
        __syncthreads();
        int w = tid >> 5, lane = tid & 31;
        if (w < NOV_ROWS) {
            int b = b0 + w; if (b >= B_) b = B_ - 1;
            float acc = 0.f;
            for (int j = lane; j < 200; j += 32)
                acc += st[w * 200 + j] * wd[w * 200 + j] - ps[w * 200 + j];
            int ap = apos[b * S_ + t]; ap = ap < 0 ? 0 : (ap > 50 ? 50 : ap);
            int rp = rpos[b * S_ + t]; rp = rp < 0 ? 0 : (rp > 4 ? 4 : rp);
            for (int p = lane; p < 50; p += 32)
                acc += apos_table[ap * 50 + p] * apos_w[p] + rpos_table[rp * 50 + p] * rpos_w[p];
            for (int off = 16; off; off >>= 1) acc += __shfl_down_sync(0xffffffffu, acc, off);
            if (lane == 0) {
                float logit = acc + s_scal;
                if (b0 + w < B_) out[(size_t)(b0 + w) * S_ + t] = logit;
                gsig[w] = 1.f / (1.f + __expf(-logit));
            }
        }
        __syncthreads();
        for (int i = tid; i < NOV_ROWS * 200; i += 256) {
            int r = i / 200;
            sum_s[i] += st[i] * gsig[r];
        }
        __syncthreads();
    }
}

// ---------------- host launch ----------------
static float* sym_addr(const void* sym) {
    void* p = nullptr;
    cudaGetSymbolAddress(&p, sym);
    return (float*)p;
}

extern "C" void kernel_launch(void* const* d_in, const int* in_sizes, int n_in,
                              void* d_out, int out_size) {
    const float* seq        = (const float*)d_in[0];
    const int*   apos       = (const int*)d_in[1];
    const int*   rpos       = (const int*)d_in[2];
    const int*   length     = (const int*)d_in[3];
    const float* apos_table = (const float*)d_in[4];
    const float* rpos_table = (const float*)d_in[5];
    const float* apos_w     = (const float*)d_in[6];
    const float* apos_b     = (const float*)d_in[7];
    const float* rpos_w     = (const float*)d_in[8];
    const float* rpos_b     = (const float*)d_in[9];
    const float* Wih_f      = (const float*)d_in[10];
    const float* Whh_f      = (const float*)d_in[11];
    const float* bih_f      = (const float*)d_in[12];
    const float* bhh_f      = (const float*)d_in[13];
    const float* Wih_b      = (const float*)d_in[14];
    const float* Whh_b      = (const float*)d_in[15];
    const float* bih_b      = (const float*)d_in[16];
    const float* bhh_b      = (const float*)d_in[17];
    const float* Wsent      = (const float*)d_in[18];
    const float* bsent      = (const float*)d_in[19];
    const float* wcont      = (const float*)d_in[20];
    const float* bcont      = (const float*)d_in[21];
    const float* Wdoc1      = (const float*)d_in[22];
    const float* bdoc1      = (const float*)d_in[23];
    const float* Wdoc2      = (const float*)d_in[24];
    const float* bdoc2      = (const float*)d_in[25];
    const float* Wnov       = (const float*)d_in[26];
    const float* bnov       = (const float*)d_in[27];
    const float* bias       = (const float*)d_in[28];
    float* out = (float*)d_out;

    float* gx     = sym_addr(g_gx);
    float* sent   = sym_addr(g_sent);
    float* avg    = sym_addr(g_avg);
    float* tmp    = sym_addr(g_tmp);
    float* doc    = sym_addr(g_doc);
    float4* wqf   = (float4*)sym_addr(g_Wqf);
    float4* wqb   = (float4*)sym_addr(g_Wqb);
    float4* wnq   = (float4*)sym_addr(g_Wnq);
    __half* Ahi = (__half*)sym_addr(g_Ahi);
    __half* Alo = (__half*)sym_addr(g_Alo);
    __half* Hhi = (__half*)sym_addr(g_Hhi);
    __half* Hlo = (__half*)sym_addr(g_Hlo);
    __half* Bgx = (__half*)sym_addr(g_Bgx);
    __half* Bse = (__half*)sym_addr(g_Bse);

    cudaFuncSetAttribute(mma_gemm<0>, cudaFuncAttributeMaxDynamicSharedMemorySize, MMA_SMEM);
    cudaFuncSetAttribute(mma_gemm<1>, cudaFuncAttributeMaxDynamicSharedMemorySize, MMA_SMEM);

    // launch 1: all scan-weight packs
    pack_all<<<(70000 + 255) / 256, 256>>>(Whh_f, Whh_b, Wnov, wqf, wqb, wnq);
    // launch 2: gx-side conversions (weights + seq hi/lo)
    conv_prep<<<1600 + (int)(((size_t)M_ * KP_GX + 255) / 256), 256>>>(
        Wih_f, Wih_b, seq, Bgx, Ahi, Alo);
    // launch 3: combined gx GEMM [51200,1200]
    mma_gemm<0><<<dim3(NP_GX / 128, M_ / 128), 256, MMA_SMEM>>>(
        Ahi, Alo, Bgx, bih_f, bih_b, 600, gx, NGX, NGX, KP_GX);
    // launch 4 (profiled): GRU recurrence
    gru_kernel<<<dim3(74, 2), 608, (GRU_ROWS * 800) * 4>>>(
        gx, wqf, wqb, bhh_f, bhh_b, Hhi, Hlo);

    // sent-weight conversion + sent GEMM
    conv_f16<<<((size_t)NP_SENT * KP_SENT + 255) / 256, 256>>>(
        Wsent, 200, 2 * H_, KP_SENT, NP_SENT, Bse);
    mma_gemm<1><<<dim3(NP_SENT / 128, M_ / 128), 256, MMA_SMEM>>>(
        Hhi, Hlo, Bse, bsent, bsent, H_, sent, H_, H_, KP_SENT);

    // avg + doc MLP (small fp32 path)
    avg_kernel<<<(B_ * H_ + 255) / 256, 256>>>(sent, length, avg);
    sgemm_nt<2><<<dim3(2, 8), 256>>>(avg, Wdoc1, bdoc1, tmp, B_, H_, H_);
    sgemm_nt<0><<<dim3(2, 8), 256>>>(tmp, Wdoc2, bdoc2, doc, B_, H_, H_);

    // novelty scan + fused base -> output
    nov_kernel<<<148, 256>>>(sent, wnq, bnov, wcont, doc, apos, rpos,
                             apos_table, rpos_table, apos_w, rpos_w,
                             apos_b, rpos_b, bcont, bias, out);
}

// round 11
// speedup vs baseline: 1.3117x; 1.3117x over previous
#include <cuda_runtime.h>
#include <cuda_fp16.h>
#include <math.h>
#include <stdint.h>

#define B_   1024
#define S_   50
#define E_   300
#define H_   200
#define M_   51200
#define NGX  1200          // stacked f|b gate width
#define KP_GX   320        // K=300 padded
#define KP_SENT 416        // K=400 padded
#define NP_GX   1280
#define NP_SENT 256
#define GRU_ROWS 14
#define NOV_ROWS 7

// ---------------- scratch (device globals; no allocations) ----------------
__device__ __align__(256) __half g_Ahi[(size_t)M_ * KP_GX];
__device__ __align__(256) __half g_Alo[(size_t)M_ * KP_GX];
__device__ __align__(256) __half g_Hhi[(size_t)M_ * KP_SENT];   // pad cols stay 0
__device__ __align__(256) __half g_Hlo[(size_t)M_ * KP_SENT];
__device__ __align__(256) __half g_Bgx[(size_t)NP_GX * KP_GX];
__device__ __align__(256) __half g_Bse[(size_t)NP_SENT * KP_SENT];
__device__ float g_gx[(size_t)M_ * NGX];
__device__ float g_sent[(size_t)M_ * H_];
__device__ float g_avg[B_ * H_];
__device__ float g_tmp[B_ * H_];
__device__ float g_doc[B_ * H_];
__device__ float g_Wqf[H_ * 3 * H_];
__device__ float g_Wqb[H_ * 3 * H_];
__device__ float g_Wnq[H_ * H_];

// ---------------- helpers ----------------
__device__ __forceinline__ uint32_t smem_u32(const void* p) {
    uint32_t a;
    asm("{ .reg .u64 t; cvta.to.shared.u64 t, %1; cvt.u32.u64 %0, t; }" : "=r"(a) : "l"(p));
    return a;
}
__device__ __forceinline__ void ldm4(uint32_t* r, uint32_t addr) {
    asm volatile("ldmatrix.sync.aligned.m8n8.x4.shared.b16 {%0,%1,%2,%3}, [%4];"
        : "=r"(r[0]), "=r"(r[1]), "=r"(r[2]), "=r"(r[3]) : "r"(addr));
}
__device__ __forceinline__ void mma_f16(float* c, const uint32_t* a, const uint32_t* b) {
    asm volatile(
        "mma.sync.aligned.m16n8k16.row.col.f32.f16.f16.f32 "
        "{%0,%1,%2,%3}, {%4,%5,%6,%7}, {%8,%9}, {%0,%1,%2,%3};"
        : "+f"(c[0]), "+f"(c[1]), "+f"(c[2]), "+f"(c[3])
        : "r"(a[0]), "r"(a[1]), "r"(a[2]), "r"(a[3]), "r"(b[0]), "r"(b[1]));
}
__device__ __forceinline__ float2 ffma2(float2 a, float2 b, float2 c) {
    unsigned long long ua = *(unsigned long long*)&a;
    unsigned long long ub = *(unsigned long long*)&b;
    unsigned long long uc = *(unsigned long long*)&c;
    unsigned long long r;
    asm("fma.rn.f32x2 %0, %1, %2, %3;" : "=l"(r) : "l"(ua), "l"(ub), "l"(uc));
    return *(float2*)&r;
}
#define CP_ASYNC16(dst, src) \
    asm volatile("cp.async.cg.shared.global [%0], [%1], 16;" :: "r"(dst), "l"(src))
#define CP_COMMIT() asm volatile("cp.async.commit_group;")
#define CP_WAIT0() asm volatile("cp.async.wait_group 0;")
#define CP_WAIT1() asm volatile("cp.async.wait_group 1;")

// ---------------- combined weight pack for scans (one launch) ----------------
__global__ void pack_all(const float* __restrict__ Whh_f, const float* __restrict__ Whh_b,
                         const float* __restrict__ Wnov,
                         float4* __restrict__ wqf, float4* __restrict__ wqb,
                         float4* __restrict__ wnq) {
    int i = blockIdx.x * blockDim.x + threadIdx.x;
    const float* src;
    float4* dst;
    int G, idx;
    if (i < 30000)      { src = Whh_f; dst = wqf; G = 600; idx = i; }
    else if (i < 60000) { src = Whh_b; dst = wqb; G = 600; idx = i - 30000; }
    else if (i < 70000) { src = Wnov;  dst = wnq; G = 200; idx = i - 60000; }
    else return;
    int k4 = idx / G, g = idx % G;
    const float* s = src + (size_t)g * 200 + 4 * k4;
    dst[idx] = make_float4(s[0], s[1], s[2], s[3]);
}

// ---------------- combined gx-side fp16 conversion (one launch) ----------------
__global__ void conv_prep(const float* __restrict__ Wih_f, const float* __restrict__ Wih_b,
                          const float* __restrict__ seq,
                          __half* __restrict__ Bgx,
                          __half* __restrict__ Ahi, __half* __restrict__ Alo) {
    if (blockIdx.x < 1600) {
        int i = blockIdx.x * 256 + threadIdx.x;
        if (i >= NP_GX * KP_GX) return;
        int row = i / KP_GX, k = i - row * KP_GX;
        float x = 0.f;
        if (k < E_) {
            if (row < 600) x = Wih_f[(size_t)row * E_ + k];
            else if (row < 1200) x = Wih_b[(size_t)(row - 600) * E_ + k];
        }
        Bgx[i] = __float2half_rn(x);
    } else {
        size_t i = (size_t)(blockIdx.x - 1600) * 256 + threadIdx.x;
        if (i >= (size_t)M_ * KP_GX) return;
        int row = (int)(i / KP_GX), k = (int)(i - (size_t)row * KP_GX);
        float x = (k < E_) ? seq[(size_t)row * E_ + k] : 0.f;
        __half h = __float2half_rn(x);
        Ahi[i] = h;
        Alo[i] = __float2half_rn(x - __half2float(h));
    }
}

// ---------------- generic fp32 -> fp16 conversion (sent weights) ----------------
__global__ void conv_f16(const float* __restrict__ X0,
                         int rows0, int K, int Kpad, int totalRows,
                         __half* __restrict__ hi) {
    int i = blockIdx.x * blockDim.x + threadIdx.x;
    if (i >= totalRows * Kpad) return;
    int row = i / Kpad, k = i - row * Kpad;
    float x = (k < K && row < rows0) ? X0[(size_t)row * K + k] : 0.f;
    hi[i] = __float2half_rn(x);
}

// ---------------- 2-pass split-fp16 tensor-core GEMM (mma.sync) ----------------
#define NSTAGE 3
#define STAGE_BYTES 30720
#define MMA_SMEM (NSTAGE * STAGE_BYTES)

template <int ACT>
__global__ void __launch_bounds__(256, 2)
mma_gemm(const __half* __restrict__ Ahi, const __half* __restrict__ Alo,
         const __half* __restrict__ Bm,
         const float* __restrict__ bias0, const float* __restrict__ bias1, int nsplit,
         float* __restrict__ C, int ldc, int Nvalid, int Kpad) {
    extern __shared__ __align__(16) __half smbuf[];
    uint32_t sb = smem_u32(smbuf);
    int tid = threadIdx.x;
    int w = tid >> 5, lane = tid & 31;
    int wm = (w >> 1) * 32, wn = (w & 1) * 64;
    int m0 = blockIdx.y * 128, n0 = blockIdx.x * 128;

    const __half* gsrc0 = Ahi + (size_t)m0 * Kpad;
    const __half* gsrc1 = Alo + (size_t)m0 * Kpad;
    const __half* gsrc2 = Bm + (size_t)n0 * Kpad;

    float acc[2][8][4];
#pragma unroll
    for (int i = 0; i < 2; i++)
#pragma unroll
        for (int j = 0; j < 8; j++)
#pragma unroll
            for (int e = 0; e < 4; e++) acc[i][j][e] = 0.f;

    int rowA = ((lane >> 3) & 1) * 8 + (lane & 7);
    int kA   = ((lane >> 4) & 1) * 8;
    int rowB = ((lane >> 4) & 1) * 8 + (lane & 7);
    int kB   = ((lane >> 3) & 1) * 8;

    int nst = Kpad / 32;
    auto load_stage = [&](int s) {
        int buf = s % NSTAGE;
        int k0 = s * 32;
#pragma unroll
        for (int i = 0; i < 6; i++) {
            int t = tid + i * 256;
            int mat = t >> 9;
            int c = t & 511;
            int row = c >> 2, kc = c & 3;
            uint32_t dst = sb + buf * STAGE_BYTES + mat * 10240 + row * 80 + kc * 16;
            const __half* src =
                (mat == 0 ? gsrc0 : mat == 1 ? gsrc1 : gsrc2)
                + (size_t)row * Kpad + k0 + kc * 8;
            CP_ASYNC16(dst, src);
        }
        CP_COMMIT();
    };

    load_stage(0);
    if (nst > 1) load_stage(1);
    for (int s = 0; s < nst; s++) {
        if (s + 2 < nst) {
            load_stage(s + 2);
            asm volatile("cp.async.wait_group 2;");
        } else if (s + 1 < nst) {
            CP_WAIT1();
        } else {
            CP_WAIT0();
        }
        __syncthreads();
        uint32_t base = sb + (s % NSTAGE) * STAGE_BYTES;
#pragma unroll
        for (int k16 = 0; k16 < 32; k16 += 16) {
            uint32_t ah[2][4], al[2][4];
#pragma unroll
            for (int ma = 0; ma < 2; ma++) {
                uint32_t off = (uint32_t)(((wm + ma * 16 + rowA) * 40 + k16 + kA) * 2);
                ldm4(ah[ma], base + off);
                ldm4(al[ma], base + 10240 + off);
            }
            uint32_t bh[4][4];
#pragma unroll
            for (int nb = 0; nb < 4; nb++) {
                uint32_t off = (uint32_t)(((wn + nb * 16 + rowB) * 40 + k16 + kB) * 2);
                ldm4(bh[nb], base + 20480 + off);
            }
#pragma unroll
            for (int ma = 0; ma < 2; ma++)
#pragma unroll
                for (int na = 0; na < 8; na++)
                    mma_f16(acc[ma][na], ah[ma], &bh[na >> 1][(na & 1) * 2]);
#pragma unroll
            for (int ma = 0; ma < 2; ma++)
#pragma unroll
                for (int na = 0; na < 8; na++)
                    mma_f16(acc[ma][na], al[ma], &bh[na >> 1][(na & 1) * 2]);
        }
        __syncthreads();
    }

    int r0 = m0 + wm + (lane >> 2);
    int cb = n0 + wn + (lane & 3) * 2;
#pragma unroll
    for (int ma = 0; ma < 2; ma++) {
        int r = r0 + ma * 16;
#pragma unroll
        for (int na = 0; na < 8; na++) {
            int col = cb + na * 8;
            if (col < Nvalid) {
                float b0v = (col < nsplit) ? bias0[col] : bias1[col - nsplit];
                float b1v = (col + 1 < nsplit) ? bias0[col + 1] : bias1[col + 1 - nsplit];
                float2 v0 = make_float2(acc[ma][na][0] + b0v, acc[ma][na][1] + b1v);
                float2 v1 = make_float2(acc[ma][na][2] + b0v, acc[ma][na][3] + b1v);
                if (ACT == 1) {
                    v0.x = fmaxf(v0.x, 0.f); v0.y = fmaxf(v0.y, 0.f);
                    v1.x = fmaxf(v1.x, 0.f); v1.y = fmaxf(v1.y, 0.f);
                }
                *(float2*)&C[(size_t)r * ldc + col] = v0;
                *(float2*)&C[(size_t)(r + 8) * ldc + col] = v1;
            }
        }
    }
}

// ---------------- small fp32 SGEMM (doc MLP only) ----------------
template <int ACT>
__global__ void __launch_bounds__(256, 2)
sgemm_nt(const float* __restrict__ A, const float* __restrict__ Bm,
         const float* __restrict__ bias, float* __restrict__ C,
         int M, int N, int K) {
    __shared__ float As[2][8][128];
    __shared__ float Bs[2][8][128];
    int tid = threadIdx.x;
    int tx = tid & 15, ty = tid >> 4;
    int m0 = blockIdx.y * 128, n0 = blockIdx.x * 128;
    int lr = tid >> 1, lq = tid & 1;
    int m = m0 + lr, n = n0 + lr;
    bool nok = (n < N);
    const float* Arow = A + (size_t)m * K;
    const float* Brow = Bm + (size_t)n * K;
    float2 acc[8][4];
#pragma unroll
    for (int i = 0; i < 8; i++)
#pragma unroll
        for (int j = 0; j < 4; j++) acc[i][j] = make_float2(0.f, 0.f);
    float av[4], bv[4];
    auto load_chunk = [&](int k0) {
        int k = k0 + lq * 4;
#pragma unroll
        for (int i = 0; i < 4; i++) {
            av[i] = (k + i < K) ? Arow[k + i] : 0.f;
            bv[i] = (nok && k + i < K) ? Brow[k + i] : 0.f;
        }
    };
    auto store_chunk = [&](int buf) {
#pragma unroll
        for (int i = 0; i < 4; i++) {
            As[buf][lq * 4 + i][lr] = av[i];
            Bs[buf][lq * 4 + i][lr] = bv[i];
        }
    };
    auto compute = [&](int buf) {
#pragma unroll
        for (int kk = 0; kk < 8; kk++) {
            float4 a0 = *(const float4*)&As[buf][kk][ty * 8];
            float4 a1 = *(const float4*)&As[buf][kk][ty * 8 + 4];
            float4 b0 = *(const float4*)&Bs[buf][kk][tx * 8];
            float4 b1 = *(const float4*)&Bs[buf][kk][tx * 8 + 4];
            float a[8] = {a0.x, a0.y, a0.z, a0.w, a1.x, a1.y, a1.z, a1.w};
            float2 b2[4] = {make_float2(b0.x, b0.y), make_float2(b0.z, b0.w),
                            make_float2(b1.x, b1.y), make_float2(b1.z, b1.w)};
#pragma unroll
            for (int i = 0; i < 8; i++) {
                float2 ad = make_float2(a[i], a[i]);
#pragma unroll
                for (int j = 0; j < 4; j++) acc[i][j] = ffma2(ad, b2[j], acc[i][j]);
            }
        }
    };
    int nt = (K + 7) / 8;
    load_chunk(0);
    store_chunk(0);
    __syncthreads();
    int cur = 0;
    for (int t = 1; t < nt; t++) {
        load_chunk(t * 8);
        compute(cur);
        store_chunk(cur ^ 1);
        __syncthreads();
        cur ^= 1;
    }
    compute(cur);
#pragma unroll
    for (int i = 0; i < 8; i++) {
        int mm = m0 + ty * 8 + i;
#pragma unroll
        for (int j = 0; j < 4; j++) {
            int nn = n0 + tx * 8 + j * 2;
            if (nn + 1 < N) {
                float2 v = acc[i][j];
                if (bias) { v.x += bias[nn]; v.y += bias[nn + 1]; }
                if (ACT == 1) { v.x = fmaxf(v.x, 0.f); v.y = fmaxf(v.y, 0.f); }
                if (ACT == 2) { v.x = tanhf(v.x); v.y = tanhf(v.y); }
                *(float2*)&C[(size_t)mm * N + nn] = v;
            } else if (nn < N) {
                float v = acc[i][j].x + (bias ? bias[nn] : 0.f);
                if (ACT == 1) v = fmaxf(v, 0.f);
                if (ACT == 2) v = tanhf(v);
                C[(size_t)mm * N + nn] = v;
            }
        }
    }
}

// ---------------- bidirectional GRU recurrence (persistent, 148 blocks) --------
// gx rows for the step are cp.async'd into smem at loop top; the matvec covers
// the copy latency, so phase B reads smem instead of stalling on DRAM.
#define GRU_SMEM ((GRU_ROWS * 200 + GRU_ROWS * 600 + GRU_ROWS * 600) * 4)  // 78400
__global__ void __launch_bounds__(608, 1)
gru_kernel(const float* __restrict__ gx,
           const float4* __restrict__ Wqf, const float4* __restrict__ Wqb,
           const float* __restrict__ bhhf, const float* __restrict__ bhhb,
           __half* __restrict__ Hhi, __half* __restrict__ Hlo) {
    extern __shared__ float sm[];
    float* hs  = sm;                      // [14][200]
    float* ghs = sm + GRU_ROWS * 200;     // [14][600]
    float* pg  = sm + GRU_ROWS * 800;     // [14][600] gx staging
    uint32_t pg_addr = smem_u32(pg);
    int dir = blockIdx.y;
    const float4* Wq = dir ? Wqb : Wqf;
    const float* bhh = dir ? bhhb : bhhf;
    int b0 = blockIdx.x * GRU_ROWS;
    int tid = threadIdx.x;

    for (int i = tid; i < GRU_ROWS * 200; i += blockDim.x) hs[i] = 0.f;
    __syncthreads();

    for (int t = 0; t < S_; t++) {
        int s = dir ? (S_ - 1 - t) : t;
        // stage gx rows for this step (2100 x 16B, coalesced)
        for (int q = tid; q < GRU_ROWS * 150; q += 608) {
            int r = q / 150, c = q - r * 150;
            int b = b0 + r;
            int bc = b < B_ ? b : B_ - 1;
            const float* src = gx + (size_t)(bc * S_ + s) * NGX + dir * 600 + c * 4;
            CP_ASYNC16(pg_addr + (uint32_t)(r * 600 + c * 4) * 4, src);
        }
        CP_COMMIT();
        if (tid < 600) {
            float2 acc2[GRU_ROWS];
#pragma unroll
            for (int r = 0; r < GRU_ROWS; r++) acc2[r] = make_float2(0.f, 0.f);
            for (int k4 = 0; k4 < 50; k4++) {
                float4 w = Wq[k4 * 600 + tid];
                float2 w01 = make_float2(w.x, w.y);
                float2 w23 = make_float2(w.z, w.w);
#pragma unroll
                for (int r = 0; r < GRU_ROWS; r++) {
                    float4 h4 = *(const float4*)&hs[r * 200 + k4 * 4];
                    acc2[r] = ffma2(w01, make_float2(h4.x, h4.y), acc2[r]);
                    acc2[r] = ffma2(w23, make_float2(h4.z, h4.w), acc2[r]);
                }
            }
            float bb = bhh[tid];
#pragma unroll
            for (int r = 0; r < GRU_ROWS; r++) ghs[r * 600 + tid] = acc2[r].x + acc2[r].y + bb;
        }
        CP_WAIT0();
        __syncthreads();
        for (int idx = tid; idx < GRU_ROWS * 200; idx += blockDim.x) {
            int r = idx / 200, j = idx % 200;
            int b = b0 + r;
            float gr = ghs[r * 600 + j];
            float gz = ghs[r * 600 + 200 + j];
            float gn = ghs[r * 600 + 400 + j];
            float xr = pg[r * 600 + j];
            float xz = pg[r * 600 + 200 + j];
            float xn = pg[r * 600 + 400 + j];
            float rg = 1.f / (1.f + __expf(-(xr + gr)));
            float zg = 1.f / (1.f + __expf(-(xz + gz)));
            float nn = tanhf(xn + rg * gn);
            float hprev = hs[r * 200 + j];
            float hnew = (1.f - zg) * nn + zg * hprev;
            hs[r * 200 + j] = hnew;
            if (b < B_) {
                size_t o = (size_t)(b * S_ + s) * KP_SENT + dir * 200 + j;
                __half hb = __float2half_rn(hnew);
                Hhi[o] = hb;
                Hlo[o] = __float2half_rn(hnew - __half2float(hb));
            }
        }
        __syncthreads();
    }
}

// ---------------- avg over sequence ----------------
__global__ void avg_kernel(const float* __restrict__ sent, const int* __restrict__ length,
                           float* __restrict__ avg) {
    int i = blockIdx.x * blockDim.x + threadIdx.x;
    if (i < B_ * H_) {
        int b = i / H_, h = i % H_;
        float s = 0.f;
        for (int t = 0; t < S_; t++) s += sent[((size_t)(b * S_ + t)) * H_ + h];
        avg[i] = s / (float)length[b];
    }
}

// ---------------- novelty scan + fused base (148 blocks x 7 rows) --------------
// sent rows double-buffered via cp.async: prefetch t+1 while computing t.
__global__ void __launch_bounds__(256, 1)
nov_kernel(const float* __restrict__ sent, const float4* __restrict__ Wnq,
           const float* __restrict__ bnov,
           const float* __restrict__ wcont, const float* __restrict__ doc,
           const int* __restrict__ apos, const int* __restrict__ rpos,
           const float* __restrict__ apos_table, const float* __restrict__ rpos_table,
           const float* __restrict__ apos_w, const float* __restrict__ rpos_w,
           const float* __restrict__ apos_b, const float* __restrict__ rpos_b,
           const float* __restrict__ bcont, const float* __restrict__ bias,
           float* __restrict__ out) {
    __shared__ float sum_s[NOV_ROWS * 200];
    __shared__ float st2[2][NOV_ROWS * 200];
    __shared__ float ps[NOV_ROWS * 200];
    __shared__ float wd[NOV_ROWS * 200];
    __shared__ float gsig[8];
    __shared__ float s_scal;
    int tid = threadIdx.x;
    int b0 = blockIdx.x * NOV_ROWS;
    uint32_t st_addr = smem_u32(st2);
    if (tid == 0) s_scal = *bcont + *apos_b + *rpos_b + *bias;
    for (int i = tid; i < NOV_ROWS * 200; i += 256) {
        int r = i / 200, j = i % 200;
        int b = b0 + r; if (b >= B_) b = B_ - 1;
        sum_s[i] = 0.f;
        wd[i] = wcont[j] + doc[(size_t)b * 200 + j];
    }
    auto stage_st = [&](int t, int buf) {
        for (int q = tid; q < NOV_ROWS * 50; q += 256) {
            int r = q / 50, c = q - r * 50;
            int b = b0 + r; if (b >= B_) b = B_ - 1;
            const float* src = sent + (size_t)(b * S_ + t) * 200 + c * 4;
            CP_ASYNC16(st_addr + (uint32_t)(buf * NOV_ROWS * 200 + r * 200 + c * 4) * 4, src);
        }
        CP_COMMIT();
    };
    stage_st(0, 0);
    int cur = 0;
    for (int t = 0; t < S_; t++) {
        if (t + 1 < S_) {
            stage_st(t + 1, cur ^ 1);
            CP_WAIT1();
        } else {
            CP_WAIT0();
        }
        __syncthreads();
        const float* st = st2[cur];
        if (tid < 200) {
            float2 acc2[NOV_ROWS];
#pragma unroll
            for (int r = 0; r < NOV_ROWS; r++) acc2[r] = make_float2(0.f, 0.f);
            for (int k4 = 0; k4 < 50; k4++) {
                float4 w = Wnq[k4 * 200 + tid];
                float2 w01 = make_float2(w.x, w.y);
                float2 w23 = make_float2(w.z, w.w);
#pragma unroll
                for (int r = 0; r < NOV_ROWS; r++) {
                    float4 h4 = *(const float4*)&st[r * 200 + k4 * 4];
                    acc2[r] = ffma2(w01, make_float2(h4.x, h4.y), acc2[r]);
                    acc2[r] = ffma2(w23, make_float2(h4.z, h4.w), acc2[r]);
                }
            }
            float bb = bnov[tid];
#pragma unroll
            for (int r = 0; r < NOV_ROWS; r++)
                ps[r * 200 + tid] = (acc2[r].x + acc2[r].y + bb) * tanhf(sum_s[r * 200 + tid]);
        }
        __syncthreads();
        int w = tid >> 5, lane = tid & 31;
        if (w < NOV_ROWS) {
            int b = b0 + w; if (b >= B_) b = B_ - 1;
            float acc = 0.f;
            for (int j = lane; j < 200; j += 32)
                acc += st[w * 200 + j] * wd[w * 200 + j] - ps[w * 200 + j];
            int ap = apos[b * S_ + t]; ap = ap < 0 ? 0 : (ap > 50 ? 50 : ap);
            int rp = rpos[b * S_ + t]; rp = rp < 0 ? 0 : (rp > 4 ? 4 : rp);
            for (int p = lane; p < 50; p += 32)
                acc += apos_table[ap * 50 + p] * apos_w[p] + rpos_table[rp * 50 + p] * rpos_w[p];
            for (int off = 16; off; off >>= 1) acc += __shfl_down_sync(0xffffffffu, acc, off);
            if (lane == 0) {
                float logit = acc + s_scal;
                if (b0 + w < B_) out[(size_t)(b0 + w) * S_ + t] = logit;
                gsig[w] = 1.f / (1.f + __expf(-logit));
            }
        }
        __syncthreads();
        for (int i = tid; i < NOV_ROWS * 200; i += 256) {
            int r = i / 200;
            sum_s[i] += st[i] * gsig[r];
        }
        __syncthreads();
        cur ^= 1;
    }
}

// ---------------- host launch ----------------
static float* sym_addr(const void* sym) {
    void* p = nullptr;
    cudaGetSymbolAddress(&p, sym);
    return (float*)p;
}

extern "C" void kernel_launch(void* const* d_in, const int* in_sizes, int n_in,
                              void* d_out, int out_size) {
    const float* seq        = (const float*)d_in[0];
    const int*   apos       = (const int*)d_in[1];
    const int*   rpos       = (const int*)d_in[2];
    const int*   length     = (const int*)d_in[3];
    const float* apos_table = (const float*)d_in[4];
    const float* rpos_table = (const float*)d_in[5];
    const float* apos_w     = (const float*)d_in[6];
    const float* apos_b     = (const float*)d_in[7];
    const float* rpos_w     = (const float*)d_in[8];
    const float* rpos_b     = (const float*)d_in[9];
    const float* Wih_f      = (const float*)d_in[10];
    const float* Whh_f      = (const float*)d_in[11];
    const float* bih_f      = (const float*)d_in[12];
    const float* bhh_f      = (const float*)d_in[13];
    const float* Wih_b      = (const float*)d_in[14];
    const float* Whh_b      = (const float*)d_in[15];
    const float* bih_b      = (const float*)d_in[16];
    const float* bhh_b      = (const float*)d_in[17];
    const float* Wsent      = (const float*)d_in[18];
    const float* bsent      = (const float*)d_in[19];
    const float* wcont      = (const float*)d_in[20];
    const float* bcont      = (const float*)d_in[21];
    const float* Wdoc1      = (const float*)d_in[22];
    const float* bdoc1      = (const float*)d_in[23];
    const float* Wdoc2      = (const float*)d_in[24];
    const float* bdoc2      = (const float*)d_in[25];
    const float* Wnov       = (const float*)d_in[26];
    const float* bnov       = (const float*)d_in[27];
    const float* bias       = (const float*)d_in[28];
    float* out = (float*)d_out;

    float* gx     = sym_addr(g_gx);
    float* sent   = sym_addr(g_sent);
    float* avg    = sym_addr(g_avg);
    float* tmp    = sym_addr(g_tmp);
    float* doc    = sym_addr(g_doc);
    float4* wqf   = (float4*)sym_addr(g_Wqf);
    float4* wqb   = (float4*)sym_addr(g_Wqb);
    float4* wnq   = (float4*)sym_addr(g_Wnq);
    __half* Ahi = (__half*)sym_addr(g_Ahi);
    __half* Alo = (__half*)sym_addr(g_Alo);
    __half* Hhi = (__half*)sym_addr(g_Hhi);
    __half* Hlo = (__half*)sym_addr(g_Hlo);
    __half* Bgx = (__half*)sym_addr(g_Bgx);
    __half* Bse = (__half*)sym_addr(g_Bse);

    cudaFuncSetAttribute(mma_gemm<0>, cudaFuncAttributeMaxDynamicSharedMemorySize, MMA_SMEM);
    cudaFuncSetAttribute(mma_gemm<1>, cudaFuncAttributeMaxDynamicSharedMemorySize, MMA_SMEM);
    cudaFuncSetAttribute(gru_kernel, cudaFuncAttributeMaxDynamicSharedMemorySize, GRU_SMEM);

    // launch 1: all scan-weight packs
    pack_all<<<(70000 + 255) / 256, 256>>>(Whh_f, Whh_b, Wnov, wqf, wqb, wnq);
    // launch 2: gx-side conversions (weights + seq hi/lo)
    conv_prep<<<1600 + (int)(((size_t)M_ * KP_GX + 255) / 256), 256>>>(
        Wih_f, Wih_b, seq, Bgx, Ahi, Alo);
    // launch 3: combined gx GEMM [51200,1200]
    mma_gemm<0><<<dim3(NP_GX / 128, M_ / 128), 256, MMA_SMEM>>>(
        Ahi, Alo, Bgx, bih_f, bih_b, 600, gx, NGX, NGX, KP_GX);
    // launch 4 (profiled): GRU recurrence
    gru_kernel<<<dim3(74, 2), 608, GRU_SMEM>>>(
        gx, wqf, wqb, bhh_f, bhh_b, Hhi, Hlo);

    // sent-weight conversion + sent GEMM
    conv_f16<<<((size_t)NP_SENT * KP_SENT + 255) / 256, 256>>>(
        Wsent, 200, 2 * H_, KP_SENT, NP_SENT, Bse);
    mma_gemm<1><<<dim3(NP_SENT / 128, M_ / 128), 256, MMA_SMEM>>>(
        Hhi, Hlo, Bse, bsent, bsent, H_, sent, H_, H_, KP_SENT);

    // avg + doc MLP (small fp32 path)
    avg_kernel<<<(B_ * H_ + 255) / 256, 256>>>(sent, length, avg);
    sgemm_nt<2><<<dim3(2, 8), 256>>>(avg, Wdoc1, bdoc1, tmp, B_, H_, H_);
    sgemm_nt<0><<<dim3(2, 8), 256>>>(tmp, Wdoc2, bdoc2, doc, B_, H_, H_);

    // novelty scan + fused base -> output
    nov_kernel<<<148, 256>>>(sent, wnq, bnov, wcont, doc, apos, rpos,
                             apos_table, rpos_table, apos_w, rpos_w,
                             apos_b, rpos_b, bcont, bias, out);
}

// round 13
// speedup vs baseline: 1.7877x; 1.3629x over previous
#include <cuda_runtime.h>
#include <cuda_fp16.h>
#include <math.h>
#include <stdint.h>

#define B_   1024
#define S_   50
#define E_   300
#define H_   200
#define M_   51200
#define NGX  1200
#define KP_GX   320
#define KP_SENT 416
#define NP_GX   1280
#define NP_SENT 256
#define GRU_ROWS 14
#define NOV_ROWS 7
#define GATES 608          // 600 valid, padded to 38 m16 tiles
#define NCHUNK 13
#define WCH_PITCH 16       // smem pitch (halves): 32B rows, 16B-aligned; XOR swizzle
#define WCH_BYTES (GATES * WCH_PITCH * 2)   // 19456
#define HH_PITCH 216       // smem pitch (halves) for h fragment rows (432B = 27*16)
#define GHS_PITCH 612      // fp32 ghs pitch

// ---------------- scratch (device globals; no allocations) ----------------
__device__ __align__(256) __half g_Ahi[(size_t)M_ * KP_GX];
__device__ __align__(256) __half g_Alo[(size_t)M_ * KP_GX];
__device__ __align__(256) __half g_Hhi[(size_t)M_ * KP_SENT];
__device__ __align__(256) __half g_Hlo[(size_t)M_ * KP_SENT];
__device__ __align__(256) __half g_Bgx[(size_t)NP_GX * KP_GX];
__device__ __align__(256) __half g_Bse[(size_t)NP_SENT * KP_SENT];
__device__ __align__(256) __half g_Wc[2 * NCHUNK * GATES * 16];   // fp16 Whh chunks
__device__ __align__(256) float g_gx[(size_t)M_ * NGX];
__device__ __align__(256) float g_sent[(size_t)M_ * H_];
__device__ float g_avg[B_ * H_];
__device__ float g_tmp[B_ * H_];
__device__ float g_doc[B_ * H_];
__device__ __align__(256) float g_Wnq[H_ * H_];

// ---------------- helpers ----------------
__device__ __forceinline__ uint32_t smem_u32(const void* p) {
    uint32_t a;
    asm("{ .reg .u64 t; cvta.to.shared.u64 t, %1; cvt.u32.u64 %0, t; }" : "=r"(a) : "l"(p));
    return a;
}
__device__ __forceinline__ void ldm4(uint32_t* r, uint32_t addr) {
    asm volatile("ldmatrix.sync.aligned.m8n8.x4.shared.b16 {%0,%1,%2,%3}, [%4];"
        : "=r"(r[0]), "=r"(r[1]), "=r"(r[2]), "=r"(r[3]) : "r"(addr));
}
__device__ __forceinline__ void mma_f16(float* c, const uint32_t* a, const uint32_t* b) {
    asm volatile(
        "mma.sync.aligned.m16n8k16.row.col.f32.f16.f16.f32 "
        "{%0,%1,%2,%3}, {%4,%5,%6,%7}, {%8,%9}, {%0,%1,%2,%3};"
        : "+f"(c[0]), "+f"(c[1]), "+f"(c[2]), "+f"(c[3])
        : "r"(a[0]), "r"(a[1]), "r"(a[2]), "r"(a[3]), "r"(b[0]), "r"(b[1]));
}
__device__ __forceinline__ float2 ffma2(float2 a, float2 b, float2 c) {
    unsigned long long ua = *(unsigned long long*)&a;
    unsigned long long ub = *(unsigned long long*)&b;
    unsigned long long uc = *(unsigned long long*)&c;
    unsigned long long r;
    asm("fma.rn.f32x2 %0, %1, %2, %3;" : "=l"(r) : "l"(ua), "l"(ub), "l"(uc));
    return *(float2*)&r;
}
#define CP_ASYNC16(dst, src) \
    asm volatile("cp.async.cg.shared.global [%0], [%1], 16;" :: "r"(dst), "l"(src))
#define CP_COMMIT() asm volatile("cp.async.commit_group;")
#define CP_WAIT0() asm volatile("cp.async.wait_group 0;")
#define CP_WAIT1() asm volatile("cp.async.wait_group 1;")

// ---------------- weight packs: Whh -> fp16 chunks + Wnov float4 -------------
__global__ void pack_all(const float* __restrict__ Whh_f, const float* __restrict__ Whh_b,
                         const float* __restrict__ Wnov,
                         __half* __restrict__ Wc, float4* __restrict__ wnq) {
    int i = blockIdx.x * blockDim.x + threadIdx.x;
    const int WC_TOTAL = 2 * NCHUNK * GATES * 16;
    if (i < WC_TOTAL) {
        int kk = i & 15;
        int t = i >> 4;
        int g = t % GATES; t /= GATES;
        int c = t % NCHUNK;
        int dir = t / NCHUNK;
        const float* W = dir ? Whh_b : Whh_f;
        int k = c * 16 + kk;
        float v = (g < 600 && k < 200) ? W[(size_t)g * 200 + k] : 0.f;
        Wc[i] = __float2half_rn(v);
    } else if (i < WC_TOTAL + 10000) {
        int idx = i - WC_TOTAL;
        int k4 = idx / 200, g = idx % 200;
        const float* s = Wnov + (size_t)g * 200 + 4 * k4;
        wnq[idx] = make_float4(s[0], s[1], s[2], s[3]);
    }
}

// ---------------- combined gx-side fp16 conversion ----------------
__global__ void conv_prep(const float* __restrict__ Wih_f, const float* __restrict__ Wih_b,
                          const float* __restrict__ seq,
                          __half* __restrict__ Bgx,
                          __half* __restrict__ Ahi, __half* __restrict__ Alo) {
    if (blockIdx.x < 1600) {
        int i = blockIdx.x * 256 + threadIdx.x;
        if (i >= NP_GX * KP_GX) return;
        int row = i / KP_GX, k = i - row * KP_GX;
        float x = 0.f;
        if (k < E_) {
            if (row < 600) x = Wih_f[(size_t)row * E_ + k];
            else if (row < 1200) x = Wih_b[(size_t)(row - 600) * E_ + k];
        }
        Bgx[i] = __float2half_rn(x);
    } else {
        size_t i = (size_t)(blockIdx.x - 1600) * 256 + threadIdx.x;
        if (i >= (size_t)M_ * KP_GX) return;
        int row = (int)(i / KP_GX), k = (int)(i - (size_t)row * KP_GX);
        float x = (k < E_) ? seq[(size_t)row * E_ + k] : 0.f;
        __half h = __float2half_rn(x);
        Ahi[i] = h;
        Alo[i] = __float2half_rn(x - __half2float(h));
    }
}

// ---------------- generic fp32 -> fp16 conversion (sent weights) --------------
__global__ void conv_f16(const float* __restrict__ X0,
                         int rows0, int K, int Kpad, int totalRows,
                         __half* __restrict__ hi) {
    int i = blockIdx.x * blockDim.x + threadIdx.x;
    if (i >= totalRows * Kpad) return;
    int row = i / Kpad, k = i - row * Kpad;
    float x = (k < K && row < rows0) ? X0[(size_t)row * K + k] : 0.f;
    hi[i] = __float2half_rn(x);
}

// ---------------- 2-pass split-fp16 tensor-core GEMM (mma.sync) ----------------
#define NSTAGE 3
#define STAGE_BYTES 30720
#define MMA_SMEM (NSTAGE * STAGE_BYTES)

template <int ACT>
__global__ void __launch_bounds__(256, 2)
mma_gemm(const __half* __restrict__ Ahi, const __half* __restrict__ Alo,
         const __half* __restrict__ Bm,
         const float* __restrict__ bias0, const float* __restrict__ bias1, int nsplit,
         float* __restrict__ C, int ldc, int Nvalid, int Kpad) {
    extern __shared__ __align__(16) __half smbuf[];
    uint32_t sb = smem_u32(smbuf);
    int tid = threadIdx.x;
    int w = tid >> 5, lane = tid & 31;
    int wm = (w >> 1) * 32, wn = (w & 1) * 64;
    int m0 = blockIdx.y * 128, n0 = blockIdx.x * 128;

    const __half* gsrc0 = Ahi + (size_t)m0 * Kpad;
    const __half* gsrc1 = Alo + (size_t)m0 * Kpad;
    const __half* gsrc2 = Bm + (size_t)n0 * Kpad;

    float acc[2][8][4];
#pragma unroll
    for (int i = 0; i < 2; i++)
#pragma unroll
        for (int j = 0; j < 8; j++)
#pragma unroll
            for (int e = 0; e < 4; e++) acc[i][j][e] = 0.f;

    int rowA = ((lane >> 3) & 1) * 8 + (lane & 7);
    int kA   = ((lane >> 4) & 1) * 8;
    int rowB = ((lane >> 4) & 1) * 8 + (lane & 7);
    int kB   = ((lane >> 3) & 1) * 8;

    int nst = Kpad / 32;
    auto load_stage = [&](int s) {
        int buf = s % NSTAGE;
        int k0 = s * 32;
#pragma unroll
        for (int i = 0; i < 6; i++) {
            int t = tid + i * 256;
            int mat = t >> 9;
            int c = t & 511;
            int row = c >> 2, kc = c & 3;
            uint32_t dst = sb + buf * STAGE_BYTES + mat * 10240 + row * 80 + kc * 16;
            const __half* src =
                (mat == 0 ? gsrc0 : mat == 1 ? gsrc1 : gsrc2)
                + (size_t)row * Kpad + k0 + kc * 8;
            CP_ASYNC16(dst, src);
        }
        CP_COMMIT();
    };

    load_stage(0);
    if (nst > 1) load_stage(1);
    for (int s = 0; s < nst; s++) {
        if (s + 2 < nst) {
            load_stage(s + 2);
            asm volatile("cp.async.wait_group 2;");
        } else if (s + 1 < nst) {
            CP_WAIT1();
        } else {
            CP_WAIT0();
        }
        __syncthreads();
        uint32_t base = sb + (s % NSTAGE) * STAGE_BYTES;
#pragma unroll
        for (int k16 = 0; k16 < 32; k16 += 16) {
            uint32_t ah[2][4], al[2][4];
#pragma unroll
            for (int ma = 0; ma < 2; ma++) {
                uint32_t off = (uint32_t)(((wm + ma * 16 + rowA) * 40 + k16 + kA) * 2);
                ldm4(ah[ma], base + off);
                ldm4(al[ma], base + 10240 + off);
            }
            uint32_t bh[4][4];
#pragma unroll
            for (int nb = 0; nb < 4; nb++) {
                uint32_t off = (uint32_t)(((wn + nb * 16 + rowB) * 40 + k16 + kB) * 2);
                ldm4(bh[nb], base + 20480 + off);
            }
#pragma unroll
            for (int ma = 0; ma < 2; ma++)
#pragma unroll
                for (int na = 0; na < 8; na++)
                    mma_f16(acc[ma][na], ah[ma], &bh[na >> 1][(na & 1) * 2]);
#pragma unroll
            for (int ma = 0; ma < 2; ma++)
#pragma unroll
                for (int na = 0; na < 8; na++)
                    mma_f16(acc[ma][na], al[ma], &bh[na >> 1][(na & 1) * 2]);
        }
        __syncthreads();
    }

    int r0 = m0 + wm + (lane >> 2);
    int cb = n0 + wn + (lane & 3) * 2;
#pragma unroll
    for (int ma = 0; ma < 2; ma++) {
        int r = r0 + ma * 16;
#pragma unroll
        for (int na = 0; na < 8; na++) {
            int col = cb + na * 8;
            if (col < Nvalid) {
                float b0v = (col < nsplit) ? bias0[col] : bias1[col - nsplit];
                float b1v = (col + 1 < nsplit) ? bias0[col + 1] : bias1[col + 1 - nsplit];
                float2 v0 = make_float2(acc[ma][na][0] + b0v, acc[ma][na][1] + b1v);
                float2 v1 = make_float2(acc[ma][na][2] + b0v, acc[ma][na][3] + b1v);
                if (ACT == 1) {
                    v0.x = fmaxf(v0.x, 0.f); v0.y = fmaxf(v0.y, 0.f);
                    v1.x = fmaxf(v1.x, 0.f); v1.y = fmaxf(v1.y, 0.f);
                }
                *(float2*)&C[(size_t)r * ldc + col] = v0;
                *(float2*)&C[(size_t)(r + 8) * ldc + col] = v1;
            }
        }
    }
}

// ---------------- small fp32 SGEMM (doc MLP only) ----------------
template <int ACT>
__global__ void __launch_bounds__(256, 2)
sgemm_nt(const float* __restrict__ A, const float* __restrict__ Bm,
         const float* __restrict__ bias, float* __restrict__ C,
         int M, int N, int K) {
    __shared__ float As[2][8][128];
    __shared__ float Bs[2][8][128];
    int tid = threadIdx.x;
    int tx = tid & 15, ty = tid >> 4;
    int m0 = blockIdx.y * 128, n0 = blockIdx.x * 128;
    int lr = tid >> 1, lq = tid & 1;
    int m = m0 + lr, n = n0 + lr;
    bool nok = (n < N);
    const float* Arow = A + (size_t)m * K;
    const float* Brow = Bm + (size_t)n * K;
    float2 acc[8][4];
#pragma unroll
    for (int i = 0; i < 8; i++)
#pragma unroll
        for (int j = 0; j < 4; j++) acc[i][j] = make_float2(0.f, 0.f);
    float av[4], bv[4];
    auto load_chunk = [&](int k0) {
        int k = k0 + lq * 4;
#pragma unroll
        for (int i = 0; i < 4; i++) {
            av[i] = (k + i < K) ? Arow[k + i] : 0.f;
            bv[i] = (nok && k + i < K) ? Brow[k + i] : 0.f;
        }
    };
    auto store_chunk = [&](int buf) {
#pragma unroll
        for (int i = 0; i < 4; i++) {
            As[buf][lq * 4 + i][lr] = av[i];
            Bs[buf][lq * 4 + i][lr] = bv[i];
        }
    };
    auto compute = [&](int buf) {
#pragma unroll
        for (int kk = 0; kk < 8; kk++) {
            float4 a0 = *(const float4*)&As[buf][kk][ty * 8];
            float4 a1 = *(const float4*)&As[buf][kk][ty * 8 + 4];
            float4 b0 = *(const float4*)&Bs[buf][kk][tx * 8];
            float4 b1 = *(const float4*)&Bs[buf][kk][tx * 8 + 4];
            float a[8] = {a0.x, a0.y, a0.z, a0.w, a1.x, a1.y, a1.z, a1.w};
            float2 b2[4] = {make_float2(b0.x, b0.y), make_float2(b0.z, b0.w),
                            make_float2(b1.x, b1.y), make_float2(b1.z, b1.w)};
#pragma unroll
            for (int i = 0; i < 8; i++) {
                float2 ad = make_float2(a[i], a[i]);
#pragma unroll
                for (int j = 0; j < 4; j++) acc[i][j] = ffma2(ad, b2[j], acc[i][j]);
            }
        }
    };
    int nt = (K + 7) / 8;
    load_chunk(0);
    store_chunk(0);
    __syncthreads();
    int cur = 0;
    for (int t = 1; t < nt; t++) {
        load_chunk(t * 8);
        compute(cur);
        store_chunk(cur ^ 1);
        __syncthreads();
        cur ^= 1;
    }
    compute(cur);
#pragma unroll
    for (int i = 0; i < 8; i++) {
        int mm = m0 + ty * 8 + i;
#pragma unroll
        for (int j = 0; j < 4; j++) {
            int nn = n0 + tx * 8 + j * 2;
            if (nn + 1 < N) {
                float2 v = acc[i][j];
                if (bias) { v.x += bias[nn]; v.y += bias[nn + 1]; }
                if (ACT == 1) { v.x = fmaxf(v.x, 0.f); v.y = fmaxf(v.y, 0.f); }
                if (ACT == 2) { v.x = tanhf(v.x); v.y = tanhf(v.y); }
                *(float2*)&C[(size_t)mm * N + nn] = v;
            } else if (nn < N) {
                float v = acc[i][j].x + (bias ? bias[nn] : 0.f);
                if (ACT == 1) v = fmaxf(v, 0.f);
                if (ACT == 2) v = tanhf(v);
                C[(size_t)mm * N + nn] = v;
            }
        }
    }
}

// ---------------- tensor-core GRU recurrence (persistent, 148 blocks) ----------
// Per step: G[608x16] = streamed fp16 Whh chunks @ (h_hi + h_lo) fp16 fragments.
// W tile: 32B rows (16B-aligned), XOR-swizzled 16B halves for bank spread.
#define GRU_SMEM 136704
__global__ void __launch_bounds__(608, 1)
gru_kernel(const float* __restrict__ gx, const __half* __restrict__ Wc,
           const float* __restrict__ bhhf, const float* __restrict__ bhhb,
           __half* __restrict__ Hhi, __half* __restrict__ Hlo) {
    extern __shared__ float sm[];
    float* hs   = sm;                       // [14][200] fp32 state
    float* ghs  = sm + 2800;                // [16][612] fp32 gate outputs
    float* pg   = sm + 12592;               // [14][600] gx staging
    __half* hh_hi = (__half*)(sm + 20992);  // [16][216] fp16 h hi
    __half* hh_lo = hh_hi + 16 * HH_PITCH;  // [16][216] fp16 h lo
    uint32_t pg_addr = smem_u32(pg);
    uint32_t hh_hi_a = smem_u32(hh_hi);
    uint32_t hh_lo_a = smem_u32(hh_lo);
    uint32_t wb_a    = smem_u32(sm + 24448);  // 2 x 19456 B W chunk buffers

    int dir = blockIdx.y;
    const float* bhh = dir ? bhhb : bhhf;
    const __half* WcD = Wc + (size_t)dir * NCHUNK * GATES * 16;
    int b0 = blockIdx.x * GRU_ROWS;
    int tid = threadIdx.x;
    int wid = tid >> 5, lane = tid & 31;
    int mb = wid * 32;                       // this warp's 2 m16 tiles: gates [mb, mb+32)

    int rowA = ((lane >> 3) & 1) * 8 + (lane & 7);
    int kA   = ((lane >> 4) & 1) * 8;
    int rowB = ((lane >> 4) & 1) * 8 + (lane & 7);
    int kB   = ((lane >> 3) & 1) * 8;
    int kpartA = kA >> 3;                    // 0 or 1 (which 16B half-row)

    // preload per-thread gate biases (4 gate rows this thread writes)
    float bias_r[4];
#pragma unroll
    for (int q = 0; q < 4; q++) {
        int g = mb + q * 8 + (lane >> 2);
        bias_r[q] = (g < 600) ? bhh[g] : 0.f;
    }

    // zero state
    for (int i = tid; i < 2800; i += 608) hs[i] = 0.f;
    for (int i = tid; i < 16 * HH_PITCH; i += 608) { hh_hi[i] = __half(0.f); hh_lo[i] = __half(0.f); }
    __syncthreads();

    auto stage_W = [&](int c, int buf) {
        for (int q = tid; q < GATES * 2; q += 608) {
            int row = q >> 1, part = q & 1;
            int psw = part ^ ((row >> 2) & 1);   // XOR swizzle, 16B granule
            const __half* src = WcD + ((size_t)c * GATES + row) * 16 + part * 8;
            CP_ASYNC16(wb_a + buf * WCH_BYTES + row * 32 + psw * 16, src);
        }
    };

    for (int t = 0; t < S_; t++) {
        int s = dir ? (S_ - 1 - t) : t;
        // stage gx + first two W chunks
        for (int q = tid; q < GRU_ROWS * 150; q += 608) {
            int r = q / 150, c = q - r * 150;
            int b = b0 + r;
            int bc = b < B_ ? b : B_ - 1;
            const float* src = gx + (size_t)(bc * S_ + s) * NGX + dir * 600 + c * 4;
            CP_ASYNC16(pg_addr + (uint32_t)(r * 600 + c * 4) * 4, src);
        }
        stage_W(0, 0);
        CP_COMMIT();
        stage_W(1, 1);
        CP_COMMIT();

        float acc[2][2][4];
#pragma unroll
        for (int i = 0; i < 2; i++)
#pragma unroll
            for (int j = 0; j < 2; j++)
#pragma unroll
                for (int e = 0; e < 4; e++) acc[i][j][e] = 0.f;

        for (int c = 0; c < NCHUNK; c++) {
            if (c < NCHUNK - 1) CP_WAIT1(); else CP_WAIT0();
            __syncthreads();
            uint32_t wb = wb_a + (c & 1) * WCH_BYTES;
            uint32_t aw[2][4], bhi[4], blo[4];
#pragma unroll
            for (int mt = 0; mt < 2; mt++) {
                int rg = mb + mt * 16 + rowA;
                int psw = kpartA ^ ((rg >> 2) & 1);
                ldm4(aw[mt], wb + (uint32_t)(rg * 32 + psw * 16));
            }
            {
                uint32_t hoff = (uint32_t)(rowB * HH_PITCH + c * 16 + kB) * 2;
                ldm4(bhi, hh_hi_a + hoff);
                ldm4(blo, hh_lo_a + hoff);
            }
#pragma unroll
            for (int mt = 0; mt < 2; mt++)
#pragma unroll
                for (int n8 = 0; n8 < 2; n8++) {
                    mma_f16(acc[mt][n8], aw[mt], &bhi[n8 * 2]);
                    mma_f16(acc[mt][n8], aw[mt], &blo[n8 * 2]);
                }
            __syncthreads();
            if (c + 2 < NCHUNK) {
                stage_W(c + 2, c & 1);
                CP_COMMIT();
            }
        }

        // epilogue: acc -> ghs[brow][gate] with bias
#pragma unroll
        for (int mt = 0; mt < 2; mt++) {
            int gate = mb + mt * 16 + (lane >> 2);
#pragma unroll
            for (int n8 = 0; n8 < 2; n8++) {
                int col = n8 * 8 + (lane & 3) * 2;
                ghs[col * GHS_PITCH + gate]           = acc[mt][n8][0] + bias_r[mt * 2];
                ghs[(col + 1) * GHS_PITCH + gate]     = acc[mt][n8][1] + bias_r[mt * 2];
                ghs[col * GHS_PITCH + gate + 8]       = acc[mt][n8][2] + bias_r[mt * 2 + 1];
                ghs[(col + 1) * GHS_PITCH + gate + 8] = acc[mt][n8][3] + bias_r[mt * 2 + 1];
            }
        }
        __syncthreads();

        // phase B: gate math + state update (fp32 exact), write fp16 copies
        for (int idx = tid; idx < GRU_ROWS * 200; idx += 608) {
            int r = idx / 200, j = idx % 200;
            int b = b0 + r;
            float gr = ghs[r * GHS_PITCH + j];
            float gz = ghs[r * GHS_PITCH + 200 + j];
            float gn = ghs[r * GHS_PITCH + 400 + j];
            float xr = pg[r * 600 + j];
            float xz = pg[r * 600 + 200 + j];
            float xn = pg[r * 600 + 400 + j];
            float rg = 1.f / (1.f + __expf(-(xr + gr)));
            float zg = 1.f / (1.f + __expf(-(xz + gz)));
            float nn = tanhf(xn + rg * gn);
            float hprev = hs[idx];
            float hnew = (1.f - zg) * nn + zg * hprev;
            hs[idx] = hnew;
            __half hb = __float2half_rn(hnew);
            __half hl = __float2half_rn(hnew - __half2float(hb));
            hh_hi[r * HH_PITCH + j] = hb;
            hh_lo[r * HH_PITCH + j] = hl;
            if (b < B_) {
                size_t o = (size_t)(b * S_ + s) * KP_SENT + dir * 200 + j;
                Hhi[o] = hb;
                Hlo[o] = hl;
            }
        }
        __syncthreads();
    }
}

// ---------------- avg over sequence ----------------
__global__ void avg_kernel(const float* __restrict__ sent, const int* __restrict__ length,
                           float* __restrict__ avg) {
    int i = blockIdx.x * blockDim.x + threadIdx.x;
    if (i < B_ * H_) {
        int b = i / H_, h = i % H_;
        float s = 0.f;
        for (int t = 0; t < S_; t++) s += sent[((size_t)(b * S_ + t)) * H_ + h];
        avg[i] = s / (float)length[b];
    }
}

// ---------------- novelty scan + fused base (148 blocks x 7 rows) --------------
__global__ void __launch_bounds__(256, 1)
nov_kernel(const float* __restrict__ sent, const float4* __restrict__ Wnq,
           const float* __restrict__ bnov,
           const float* __restrict__ wcont, const float* __restrict__ doc,
           const int* __restrict__ apos, const int* __restrict__ rpos,
           const float* __restrict__ apos_table, const float* __restrict__ rpos_table,
           const float* __restrict__ apos_w, const float* __restrict__ rpos_w,
           const float* __restrict__ apos_b, const float* __restrict__ rpos_b,
           const float* __restrict__ bcont, const float* __restrict__ bias,
           float* __restrict__ out) {
    __shared__ float sum_s[NOV_ROWS * 200];
    __shared__ float st2[2][NOV_ROWS * 200];
    __shared__ float ps[NOV_ROWS * 200];
    __shared__ float wd[NOV_ROWS * 200];
    __shared__ float gsig[8];
    __shared__ float s_scal;
    int tid = threadIdx.x;
    int b0 = blockIdx.x * NOV_ROWS;
    uint32_t st_addr = smem_u32(st2);
    if (tid == 0) s_scal = *bcont + *apos_b + *rpos_b + *bias;
    for (int i = tid; i < NOV_ROWS * 200; i += 256) {
        int r = i / 200, j = i % 200;
        int b = b0 + r; if (b >= B_) b = B_ - 1;
        sum_s[i] = 0.f;
        wd[i] = wcont[j] + doc[(size_t)b * 200 + j];
    }
    auto stage_st = [&](int t, int buf) {
        for (int q = tid; q < NOV_ROWS * 50; q += 256) {
            int r = q / 50, c = q - r * 50;
            int b = b0 + r; if (b >= B_) b = B_ - 1;
            const float* src = sent + (size_t)(b * S_ + t) * 200 + c * 4;
            CP_ASYNC16(st_addr + (uint32_t)(buf * NOV_ROWS * 200 + r * 200 + c * 4) * 4, src);
        }
        CP_COMMIT();
    };
    stage_st(0, 0);
    int cur = 0;
    for (int t = 0; t < S_; t++) {
        if (t + 1 < S_) {
            stage_st(t + 1, cur ^ 1);
            CP_WAIT1();
        } else {
            CP_WAIT0();
        }
        __syncthreads();
        const float* st = st2[cur];
        if (tid < 200) {
            float2 acc2[NOV_ROWS];
#pragma unroll
            for (int r = 0; r < NOV_ROWS; r++) acc2[r] = make_float2(0.f, 0.f);
            for (int k4 = 0; k4 < 50; k4++) {
                float4 w = Wnq[k4 * 200 + tid];
                float2 w01 = make_float2(w.x, w.y);
                float2 w23 = make_float2(w.z, w.w);
#pragma unroll
                for (int r = 0; r < NOV_ROWS; r++) {
                    float4 h4 = *(const float4*)&st[r * 200 + k4 * 4];
                    acc2[r] = ffma2(w01, make_float2(h4.x, h4.y), acc2[r]);
                    acc2[r] = ffma2(w23, make_float2(h4.z, h4.w), acc2[r]);
                }
            }
            float bb = bnov[tid];
#pragma unroll
            for (int r = 0; r < NOV_ROWS; r++)
                ps[r * 200 + tid] = (acc2[r].x + acc2[r].y + bb) * tanhf(sum_s[r * 200 + tid]);
        }
        __syncthreads();
        int w = tid >> 5, lane = tid & 31;
        if (w < NOV_ROWS) {
            int b = b0 + w; if (b >= B_) b = B_ - 1;
            float acc = 0.f;
            for (int j = lane; j < 200; j += 32)
                acc += st[w * 200 + j] * wd[w * 200 + j] - ps[w * 200 + j];
            int ap = apos[b * S_ + t]; ap = ap < 0 ? 0 : (ap > 50 ? 50 : ap);
            int rp = rpos[b * S_ + t]; rp = rp < 0 ? 0 : (rp > 4 ? 4 : rp);
            for (int p = lane; p < 50; p += 32)
                acc += apos_table[ap * 50 + p] * apos_w[p] + rpos_table[rp * 50 + p] * rpos_w[p];
            for (int off = 16; off; off >>= 1) acc += __shfl_down_sync(0xffffffffu, acc, off);
            if (lane == 0) {
                float logit = acc + s_scal;
                if (b0 + w < B_) out[(size_t)(b0 + w) * S_ + t] = logit;
                gsig[w] = 1.f / (1.f + __expf(-logit));
            }
        }
        __syncthreads();
        for (int i = tid; i < NOV_ROWS * 200; i += 256) {
            int r = i / 200;
            sum_s[i] += st[i] * gsig[r];
        }
        __syncthreads();
        cur ^= 1;
    }
}

// ---------------- host launch ----------------
static float* sym_addr(const void* sym) {
    void* p = nullptr;
    cudaGetSymbolAddress(&p, sym);
    return (float*)p;
}

extern "C" void kernel_launch(void* const* d_in, const int* in_sizes, int n_in,
                              void* d_out, int out_size) {
    const float* seq        = (const float*)d_in[0];
    const int*   apos       = (const int*)d_in[1];
    const int*   rpos       = (const int*)d_in[2];
    const int*   length     = (const int*)d_in[3];
    const float* apos_table = (const float*)d_in[4];
    const float* rpos_table = (const float*)d_in[5];
    const float* apos_w     = (const float*)d_in[6];
    const float* apos_b     = (const float*)d_in[7];
    const float* rpos_w     = (const float*)d_in[8];
    const float* rpos_b     = (const float*)d_in[9];
    const float* Wih_f      = (const float*)d_in[10];
    const float* Whh_f      = (const float*)d_in[11];
    const float* bih_f      = (const float*)d_in[12];
    const float* bhh_f      = (const float*)d_in[13];
    const float* Wih_b      = (const float*)d_in[14];
    const float* Whh_b      = (const float*)d_in[15];
    const float* bih_b      = (const float*)d_in[16];
    const float* bhh_b      = (const float*)d_in[17];
    const float* Wsent      = (const float*)d_in[18];
    const float* bsent      = (const float*)d_in[19];
    const float* wcont      = (const float*)d_in[20];
    const float* bcont      = (const float*)d_in[21];
    const float* Wdoc1      = (const float*)d_in[22];
    const float* bdoc1      = (const float*)d_in[23];
    const float* Wdoc2      = (const float*)d_in[24];
    const float* bdoc2      = (const float*)d_in[25];
    const float* Wnov       = (const float*)d_in[26];
    const float* bnov       = (const float*)d_in[27];
    const float* bias       = (const float*)d_in[28];
    float* out = (float*)d_out;

    float* gx     = sym_addr(g_gx);
    float* sent   = sym_addr(g_sent);
    float* avg    = sym_addr(g_avg);
    float* tmp    = sym_addr(g_tmp);
    float* doc    = sym_addr(g_doc);
    float4* wnq   = (float4*)sym_addr(g_Wnq);
    __half* Wc  = (__half*)sym_addr(g_Wc);
    __half* Ahi = (__half*)sym_addr(g_Ahi);
    __half* Alo = (__half*)sym_addr(g_Alo);
    __half* Hhi = (__half*)sym_addr(g_Hhi);
    __half* Hlo = (__half*)sym_addr(g_Hlo);
    __half* Bgx = (__half*)sym_addr(g_Bgx);
    __half* Bse = (__half*)sym_addr(g_Bse);

    cudaFuncSetAttribute(mma_gemm<0>, cudaFuncAttributeMaxDynamicSharedMemorySize, MMA_SMEM);
    cudaFuncSetAttribute(mma_gemm<1>, cudaFuncAttributeMaxDynamicSharedMemorySize, MMA_SMEM);
    cudaFuncSetAttribute(gru_kernel, cudaFuncAttributeMaxDynamicSharedMemorySize, GRU_SMEM);

    // launch 1: weight packs (Whh fp16 chunks + Wnov)
    pack_all<<<(2 * NCHUNK * GATES * 16 + 10000 + 255) / 256, 256>>>(
        Whh_f, Whh_b, Wnov, Wc, wnq);
    // launch 2: gx-side conversions
    conv_prep<<<1600 + (int)(((size_t)M_ * KP_GX + 255) / 256), 256>>>(
        Wih_f, Wih_b, seq, Bgx, Ahi, Alo);
    // launch 3: combined gx GEMM [51200,1200]
    mma_gemm<0><<<dim3(NP_GX / 128, M_ / 128), 256, MMA_SMEM>>>(
        Ahi, Alo, Bgx, bih_f, bih_b, 600, gx, NGX, NGX, KP_GX);
    // launch 4 (profiled): tensor-core GRU recurrence
    gru_kernel<<<dim3(74, 2), 608, GRU_SMEM>>>(
        gx, Wc, bhh_f, bhh_b, Hhi, Hlo);

    // sent-weight conversion + sent GEMM
    conv_f16<<<((size_t)NP_SENT * KP_SENT + 255) / 256, 256>>>(
        Wsent, 200, 2 * H_, KP_SENT, NP_SENT, Bse);
    mma_gemm<1><<<dim3(NP_SENT / 128, M_ / 128), 256, MMA_SMEM>>>(
        Hhi, Hlo, Bse, bsent, bsent, H_, sent, H_, H_, KP_SENT);

    // avg + doc MLP (small fp32 path)
    avg_kernel<<<(B_ * H_ + 255) / 256, 256>>>(sent, length, avg);
    sgemm_nt<2><<<dim3(2, 8), 256>>>(avg, Wdoc1, bdoc1, tmp, B_, H_, H_);
    sgemm_nt<0><<<dim3(2, 8), 256>>>(tmp, Wdoc2, bdoc2, doc, B_, H_, H_);

    // novelty scan + fused base -> output
    nov_kernel<<<148, 256>>>(sent, wnq, bnov, wcont, doc, apos, rpos,
                             apos_table, rpos_table, apos_w, rpos_w,
                             apos_b, rpos_b, bcont, bias, out);
}

// round 15
// speedup vs baseline: 2.0248x; 1.1326x over previous
#include <cuda_runtime.h>
#include <cuda_fp16.h>
#include <math.h>
#include <stdint.h>

#define B_   1024
#define S_   50
#define E_   300
#define H_   200
#define M_   51200
#define NGX  1200
#define KP_GX   320
#define KP_SENT 416
#define NP_GX   1280
#define NP_SENT 256
#define GRU_ROWS 14
#define NOV_ROWS 7
#define GATES 608
#define NCHUNK 13
#define WCH_BYTES (GATES * 16 * 2)      // 19456 B per k16 chunk
#define SWBUF_BYTES (3 * WCH_BYTES)     // 58368 B per super-chunk buffer
#define HH_PITCH 216
#define GHS_PITCH 612

// ---------------- scratch (device globals; no allocations) ----------------
__device__ __align__(256) __half g_Ahi[(size_t)M_ * KP_GX];
__device__ __align__(256) __half g_Alo[(size_t)M_ * KP_GX];
__device__ __align__(256) __half g_Hhi[(size_t)M_ * KP_SENT];
__device__ __align__(256) __half g_Hlo[(size_t)M_ * KP_SENT];
__device__ __align__(256) __half g_Bgx[(size_t)NP_GX * KP_GX];
__device__ __align__(256) __half g_Bse[(size_t)NP_SENT * KP_SENT];
__device__ __align__(256) __half g_Wc[2 * NCHUNK * GATES * 16];
__device__ __align__(256) float g_gx[(size_t)M_ * NGX];
__device__ __align__(256) float g_sent[(size_t)M_ * H_];
__device__ float g_avg[B_ * H_];
__device__ float g_tmp[B_ * H_];
__device__ float g_doc[B_ * H_];
__device__ __align__(256) float g_Wnq[H_ * H_];

// ---------------- helpers ----------------
__device__ __forceinline__ uint32_t smem_u32(const void* p) {
    uint32_t a;
    asm("{ .reg .u64 t; cvta.to.shared.u64 t, %1; cvt.u32.u64 %0, t; }" : "=r"(a) : "l"(p));
    return a;
}
__device__ __forceinline__ void ldm4(uint32_t* r, uint32_t addr) {
    asm volatile("ldmatrix.sync.aligned.m8n8.x4.shared.b16 {%0,%1,%2,%3}, [%4];"
        : "=r"(r[0]), "=r"(r[1]), "=r"(r[2]), "=r"(r[3]) : "r"(addr));
}
__device__ __forceinline__ void mma_f16(float* c, const uint32_t* a, const uint32_t* b) {
    asm volatile(
        "mma.sync.aligned.m16n8k16.row.col.f32.f16.f16.f32 "
        "{%0,%1,%2,%3}, {%4,%5,%6,%7}, {%8,%9}, {%0,%1,%2,%3};"
        : "+f"(c[0]), "+f"(c[1]), "+f"(c[2]), "+f"(c[3])
        : "r"(a[0]), "r"(a[1]), "r"(a[2]), "r"(a[3]), "r"(b[0]), "r"(b[1]));
}
__device__ __forceinline__ float2 ffma2(float2 a, float2 b, float2 c) {
    unsigned long long ua = *(unsigned long long*)&a;
    unsigned long long ub = *(unsigned long long*)&b;
    unsigned long long uc = *(unsigned long long*)&c;
    unsigned long long r;
    asm("fma.rn.f32x2 %0, %1, %2, %3;" : "=l"(r) : "l"(ua), "l"(ub), "l"(uc));
    return *(float2*)&r;
}
#define CP_ASYNC16(dst, src) \
    asm volatile("cp.async.cg.shared.global [%0], [%1], 16;" :: "r"(dst), "l"(src))
#define CP_COMMIT() asm volatile("cp.async.commit_group;")
#define CP_WAIT0() asm volatile("cp.async.wait_group 0;")
#define CP_WAIT1() asm volatile("cp.async.wait_group 1;")

// ---------------- weight packs: Whh -> fp16 chunks + Wnov float4 -------------
__global__ void pack_all(const float* __restrict__ Whh_f, const float* __restrict__ Whh_b,
                         const float* __restrict__ Wnov,
                         __half* __restrict__ Wc, float4* __restrict__ wnq) {
    int i = blockIdx.x * blockDim.x + threadIdx.x;
    const int WC_TOTAL = 2 * NCHUNK * GATES * 16;
    if (i < WC_TOTAL) {
        int kk = i & 15;
        int t = i >> 4;
        int g = t % GATES; t /= GATES;
        int c = t % NCHUNK;
        int dir = t / NCHUNK;
        const float* W = dir ? Whh_b : Whh_f;
        int k = c * 16 + kk;
        float v = (g < 600 && k < 200) ? W[(size_t)g * 200 + k] : 0.f;
        Wc[i] = __float2half_rn(v);
    } else if (i < WC_TOTAL + 10000) {
        int idx = i - WC_TOTAL;
        int k4 = idx / 200, g = idx % 200;
        const float* s = Wnov + (size_t)g * 200 + 4 * k4;
        wnq[idx] = make_float4(s[0], s[1], s[2], s[3]);
    }
}

// ---------------- combined gx-side fp16 conversion ----------------
__global__ void conv_prep(const float* __restrict__ Wih_f, const float* __restrict__ Wih_b,
                          const float* __restrict__ seq,
                          __half* __restrict__ Bgx,
                          __half* __restrict__ Ahi, __half* __restrict__ Alo) {
    if (blockIdx.x < 1600) {
        int i = blockIdx.x * 256 + threadIdx.x;
        if (i >= NP_GX * KP_GX) return;
        int row = i / KP_GX, k = i - row * KP_GX;
        float x = 0.f;
        if (k < E_) {
            if (row < 600) x = Wih_f[(size_t)row * E_ + k];
            else if (row < 1200) x = Wih_b[(size_t)(row - 600) * E_ + k];
        }
        Bgx[i] = __float2half_rn(x);
    } else {
        size_t i = (size_t)(blockIdx.x - 1600) * 256 + threadIdx.x;
        if (i >= (size_t)M_ * KP_GX) return;
        int row = (int)(i / KP_GX), k = (int)(i - (size_t)row * KP_GX);
        float x = (k < E_) ? seq[(size_t)row * E_ + k] : 0.f;
        __half h = __float2half_rn(x);
        Ahi[i] = h;
        Alo[i] = __float2half_rn(x - __half2float(h));
    }
}

// ---------------- generic fp32 -> fp16 conversion (sent weights) --------------
__global__ void conv_f16(const float* __restrict__ X0,
                         int rows0, int K, int Kpad, int totalRows,
                         __half* __restrict__ hi) {
    int i = blockIdx.x * blockDim.x + threadIdx.x;
    if (i >= totalRows * Kpad) return;
    int row = i / Kpad, k = i - row * Kpad;
    float x = (k < K && row < rows0) ? X0[(size_t)row * K + k] : 0.f;
    hi[i] = __float2half_rn(x);
}

// ---------------- 2-pass split-fp16 tensor-core GEMM (mma.sync) ----------------
#define NSTAGE 3
#define STAGE_BYTES 30720
#define MMA_SMEM (NSTAGE * STAGE_BYTES)

template <int ACT>
__global__ void __launch_bounds__(256, 2)
mma_gemm(const __half* __restrict__ Ahi, const __half* __restrict__ Alo,
         const __half* __restrict__ Bm,
         const float* __restrict__ bias0, const float* __restrict__ bias1, int nsplit,
         float* __restrict__ C, int ldc, int Nvalid, int Kpad) {
    extern __shared__ __align__(16) __half smbuf[];
    uint32_t sb = smem_u32(smbuf);
    int tid = threadIdx.x;
    int w = tid >> 5, lane = tid & 31;
    int wm = (w >> 1) * 32, wn = (w & 1) * 64;
    int m0 = blockIdx.y * 128, n0 = blockIdx.x * 128;

    const __half* gsrc0 = Ahi + (size_t)m0 * Kpad;
    const __half* gsrc1 = Alo + (size_t)m0 * Kpad;
    const __half* gsrc2 = Bm + (size_t)n0 * Kpad;

    float acc[2][8][4];
#pragma unroll
    for (int i = 0; i < 2; i++)
#pragma unroll
        for (int j = 0; j < 8; j++)
#pragma unroll
            for (int e = 0; e < 4; e++) acc[i][j][e] = 0.f;

    int rowA = ((lane >> 3) & 1) * 8 + (lane & 7);
    int kA   = ((lane >> 4) & 1) * 8;
    int rowB = ((lane >> 4) & 1) * 8 + (lane & 7);
    int kB   = ((lane >> 3) & 1) * 8;

    int nst = Kpad / 32;
    auto load_stage = [&](int s) {
        int buf = s % NSTAGE;
        int k0 = s * 32;
#pragma unroll
        for (int i = 0; i < 6; i++) {
            int t = tid + i * 256;
            int mat = t >> 9;
            int c = t & 511;
            int row = c >> 2, kc = c & 3;
            uint32_t dst = sb + buf * STAGE_BYTES + mat * 10240 + row * 80 + kc * 16;
            const __half* src =
                (mat == 0 ? gsrc0 : mat == 1 ? gsrc1 : gsrc2)
                + (size_t)row * Kpad + k0 + kc * 8;
            CP_ASYNC16(dst, src);
        }
        CP_COMMIT();
    };

    load_stage(0);
    if (nst > 1) load_stage(1);
    for (int s = 0; s < nst; s++) {
        if (s + 2 < nst) {
            load_stage(s + 2);
            asm volatile("cp.async.wait_group 2;");
        } else if (s + 1 < nst) {
            CP_WAIT1();
        } else {
            CP_WAIT0();
        }
        __syncthreads();
        uint32_t base = sb + (s % NSTAGE) * STAGE_BYTES;
#pragma unroll
        for (int k16 = 0; k16 < 32; k16 += 16) {
            uint32_t ah[2][4], al[2][4];
#pragma unroll
            for (int ma = 0; ma < 2; ma++) {
                uint32_t off = (uint32_t)(((wm + ma * 16 + rowA) * 40 + k16 + kA) * 2);
                ldm4(ah[ma], base + off);
                ldm4(al[ma], base + 10240 + off);
            }
            uint32_t bh[4][4];
#pragma unroll
            for (int nb = 0; nb < 4; nb++) {
                uint32_t off = (uint32_t)(((wn + nb * 16 + rowB) * 40 + k16 + kB) * 2);
                ldm4(bh[nb], base + 20480 + off);
            }
#pragma unroll
            for (int ma = 0; ma < 2; ma++)
#pragma unroll
                for (int na = 0; na < 8; na++)
                    mma_f16(acc[ma][na], ah[ma], &bh[na >> 1][(na & 1) * 2]);
#pragma unroll
            for (int ma = 0; ma < 2; ma++)
#pragma unroll
                for (int na = 0; na < 8; na++)
                    mma_f16(acc[ma][na], al[ma], &bh[na >> 1][(na & 1) * 2]);
        }
        __syncthreads();
    }

    int r0 = m0 + wm + (lane >> 2);
    int cb = n0 + wn + (lane & 3) * 2;
#pragma unroll
    for (int ma = 0; ma < 2; ma++) {
        int r = r0 + ma * 16;
#pragma unroll
        for (int na = 0; na < 8; na++) {
            int col = cb + na * 8;
            if (col < Nvalid) {
                float b0v = (col < nsplit) ? bias0[col] : bias1[col - nsplit];
                float b1v = (col + 1 < nsplit) ? bias0[col + 1] : bias1[col + 1 - nsplit];
                float2 v0 = make_float2(acc[ma][na][0] + b0v, acc[ma][na][1] + b1v);
                float2 v1 = make_float2(acc[ma][na][2] + b0v, acc[ma][na][3] + b1v);
                if (ACT == 1) {
                    v0.x = fmaxf(v0.x, 0.f); v0.y = fmaxf(v0.y, 0.f);
                    v1.x = fmaxf(v1.x, 0.f); v1.y = fmaxf(v1.y, 0.f);
                }
                *(float2*)&C[(size_t)r * ldc + col] = v0;
                *(float2*)&C[(size_t)(r + 8) * ldc + col] = v1;
            }
        }
    }
}

// ---------------- small fp32 SGEMM (doc MLP only) ----------------
template <int ACT>
__global__ void __launch_bounds__(256, 2)
sgemm_nt(const float* __restrict__ A, const float* __restrict__ Bm,
         const float* __restrict__ bias, float* __restrict__ C,
         int M, int N, int K) {
    __shared__ float As[2][8][128];
    __shared__ float Bs[2][8][128];
    int tid = threadIdx.x;
    int tx = tid & 15, ty = tid >> 4;
    int m0 = blockIdx.y * 128, n0 = blockIdx.x * 128;
    int lr = tid >> 1, lq = tid & 1;
    int m = m0 + lr, n = n0 + lr;
    bool nok = (n < N);
    const float* Arow = A + (size_t)m * K;
    const float* Brow = Bm + (size_t)n * K;
    float2 acc[8][4];
#pragma unroll
    for (int i = 0; i < 8; i++)
#pragma unroll
        for (int j = 0; j < 4; j++) acc[i][j] = make_float2(0.f, 0.f);
    float av[4], bv[4];
    auto load_chunk = [&](int k0) {
        int k = k0 + lq * 4;
#pragma unroll
        for (int i = 0; i < 4; i++) {
            av[i] = (k + i < K) ? Arow[k + i] : 0.f;
            bv[i] = (nok && k + i < K) ? Brow[k + i] : 0.f;
        }
    };
    auto store_chunk = [&](int buf) {
#pragma unroll
        for (int i = 0; i < 4; i++) {
            As[buf][lq * 4 + i][lr] = av[i];
            Bs[buf][lq * 4 + i][lr] = bv[i];
        }
    };
    auto compute = [&](int buf) {
#pragma unroll
        for (int kk = 0; kk < 8; kk++) {
            float4 a0 = *(const float4*)&As[buf][kk][ty * 8];
            float4 a1 = *(const float4*)&As[buf][kk][ty * 8 + 4];
            float4 b0 = *(const float4*)&Bs[buf][kk][tx * 8];
            float4 b1 = *(const float4*)&Bs[buf][kk][tx * 8 + 4];
            float a[8] = {a0.x, a0.y, a0.z, a0.w, a1.x, a1.y, a1.z, a1.w};
            float2 b2[4] = {make_float2(b0.x, b0.y), make_float2(b0.z, b0.w),
                            make_float2(b1.x, b1.y), make_float2(b1.z, b1.w)};
#pragma unroll
            for (int i = 0; i < 8; i++) {
                float2 ad = make_float2(a[i], a[i]);
#pragma unroll
                for (int j = 0; j < 4; j++) acc[i][j] = ffma2(ad, b2[j], acc[i][j]);
            }
        }
    };
    int nt = (K + 7) / 8;
    load_chunk(0);
    store_chunk(0);
    __syncthreads();
    int cur = 0;
    for (int t = 1; t < nt; t++) {
        load_chunk(t * 8);
        compute(cur);
        store_chunk(cur ^ 1);
        __syncthreads();
        cur ^= 1;
    }
    compute(cur);
#pragma unroll
    for (int i = 0; i < 8; i++) {
        int mm = m0 + ty * 8 + i;
#pragma unroll
        for (int j = 0; j < 4; j++) {
            int nn = n0 + tx * 8 + j * 2;
            if (nn + 1 < N) {
                float2 v = acc[i][j];
                if (bias) { v.x += bias[nn]; v.y += bias[nn + 1]; }
                if (ACT == 1) { v.x = fmaxf(v.x, 0.f); v.y = fmaxf(v.y, 0.f); }
                if (ACT == 2) { v.x = tanhf(v.x); v.y = tanhf(v.y); }
                *(float2*)&C[(size_t)mm * N + nn] = v;
            } else if (nn < N) {
                float v = acc[i][j].x + (bias ? bias[nn] : 0.f);
                if (ACT == 1) v = fmaxf(v, 0.f);
                if (ACT == 2) v = tanhf(v);
                C[(size_t)mm * N + nn] = v;
            }
        }
    }
}

// ---------------- tensor-core GRU recurrence (persistent, 148 blocks) ----------
// Super-chunks of 3 k16 chunks per barrier pair; all addressing hoisted out of
// the step loop. smem: hs|ghs|pg|hh + 2x58368B W buffers = 214528 B.
#define GRU_SMEM 214528
__global__ void __launch_bounds__(608, 1)
gru_kernel(const float* __restrict__ gx, const __half* __restrict__ Wc,
           const float* __restrict__ bhhf, const float* __restrict__ bhhb,
           __half* __restrict__ Hhi, __half* __restrict__ Hlo) {
    extern __shared__ float sm[];
    float* hs   = sm;                       // [2800]
    float* ghs  = sm + 2800;                // [16*612]
    float* pg   = sm + 12592;               // [14*600]
    __half* hh_hi = (__half*)(sm + 20992);  // [16*216]
    __half* hh_lo = hh_hi + 16 * HH_PITCH;
    uint32_t pg_addr = smem_u32(pg);
    uint32_t hh_hi_a = smem_u32(hh_hi);
    uint32_t hh_lo_a = smem_u32(hh_lo);
    uint32_t wb_a    = smem_u32(sm + 24448);  // 2 x 58368 B

    int dir = blockIdx.y;
    const float* bhh = dir ? bhhb : bhhf;
    const __half* WcD = Wc + (size_t)dir * NCHUNK * GATES * 16;
    int b0 = blockIdx.x * GRU_ROWS;
    int tid = threadIdx.x;
    int wid = tid >> 5, lane = tid & 31;
    int mb = wid * 32;

    int rowA = ((lane >> 3) & 1) * 8 + (lane & 7);
    int kA   = ((lane >> 4) & 1) * 8;
    int rowB = ((lane >> 4) & 1) * 8 + (lane & 7);
    int kB   = ((lane >> 3) & 1) * 8;
    int kpartA = kA >> 3;

    // hoisted: A-fragment byte offsets within a chunk slot
    uint32_t awoff[2];
#pragma unroll
    for (int mt = 0; mt < 2; mt++) {
        int rg = mb + mt * 16 + rowA;
        int psw = kpartA ^ ((rg >> 2) & 1);
        awoff[mt] = (uint32_t)(rg * 32 + psw * 16);
    }
    uint32_t hbase = (uint32_t)(rowB * HH_PITCH + kB) * 2;

    // hoisted: stage_W per-thread offsets (2 elements/thread)
    int row_a = tid >> 1, part_a = tid & 1;
    uint32_t wsrcA = (uint32_t)(row_a * 16 + part_a * 8);           // halves
    uint32_t wdstA = (uint32_t)(row_a * 32 + ((part_a ^ ((row_a >> 2) & 1)) * 16));
    uint32_t wsrcB = wsrcA + 304 * 16;
    uint32_t wdstB = wdstA + 304 * 32;

    // hoisted: gx staging tuples (up to 4/thread)
    int nG = 0;
    int growb[4]; int gcol[4]; uint32_t gdst[4];
    for (int q = tid; q < GRU_ROWS * 150; q += 608) {
        int r = q / 150, c = q - r * 150;
        int b = b0 + r;
        int bc = b < B_ ? b : B_ - 1;
        growb[nG] = bc * S_;
        gcol[nG] = dir * 600 + c * 4;
        gdst[nG] = pg_addr + (uint32_t)(r * 600 + c * 4) * 4;
        nG++;
    }

    // hoisted: phase-B tuples (up to 5/thread)
    int nB = 0;
    int pgo[5], gho[5], hso[5], hho[5], bvalid[5];
    size_t obase[5];
    for (int idx = tid; idx < GRU_ROWS * 200; idx += 608) {
        int r = idx / 200, j = idx - r * 200;
        int b = b0 + r;
        pgo[nB] = r * 600 + j;
        gho[nB] = r * GHS_PITCH + j;
        hso[nB] = idx;
        hho[nB] = r * HH_PITCH + j;
        bvalid[nB] = (b < B_);
        obase[nB] = (size_t)(b < B_ ? b : 0) * S_ * KP_SENT + dir * 200 + j;
        nB++;
    }

    float bias_r[4];
#pragma unroll
    for (int q = 0; q < 4; q++) {
        int g = mb + q * 8 + (lane >> 2);
        bias_r[q] = (g < 600) ? bhh[g] : 0.f;
    }

    for (int i = tid; i < 2800; i += 608) hs[i] = 0.f;
    for (int i = tid; i < 16 * HH_PITCH; i += 608) { hh_hi[i] = __half(0.f); hh_lo[i] = __half(0.f); }
    __syncthreads();

    auto stage_SW = [&](int sc, int buf) {
        int cnt = (sc == 4) ? 1 : 3;
        uint32_t dbase = wb_a + buf * SWBUF_BYTES;
        const __half* sbase = WcD + (size_t)(3 * sc) * GATES * 16;
        for (int cs = 0; cs < cnt; cs++) {
            CP_ASYNC16(dbase + cs * WCH_BYTES + wdstA, sbase + cs * GATES * 16 + wsrcA);
            CP_ASYNC16(dbase + cs * WCH_BYTES + wdstB, sbase + cs * GATES * 16 + wsrcB);
        }
    };

    for (int t = 0; t < S_; t++) {
        int s = dir ? (S_ - 1 - t) : t;
        // stage gx + W super-chunk 0 (group A), super-chunk 1 (group B)
#pragma unroll
        for (int i = 0; i < 4; i++) {
            if (i < nG) {
                const float* src = gx + (size_t)(growb[i] + s) * NGX + gcol[i];
                CP_ASYNC16(gdst[i], src);
            }
        }
        stage_SW(0, 0);
        CP_COMMIT();
        stage_SW(1, 1);
        CP_COMMIT();

        float acc[2][2][4];
#pragma unroll
        for (int i = 0; i < 2; i++)
#pragma unroll
            for (int j = 0; j < 2; j++)
#pragma unroll
                for (int e = 0; e < 4; e++) acc[i][j][e] = 0.f;

        for (int sc = 0; sc < 5; sc++) {
            if (sc < 4) CP_WAIT1(); else CP_WAIT0();
            __syncthreads();
            uint32_t wb = wb_a + (sc & 1) * SWBUF_BYTES;
            int cnt = (sc == 4) ? 1 : 3;
            int cbase = 3 * sc;
            for (int cs = 0; cs < cnt; cs++) {
                uint32_t aw[2][4], bhi[4], blo[4];
#pragma unroll
                for (int mt = 0; mt < 2; mt++)
                    ldm4(aw[mt], wb + cs * WCH_BYTES + awoff[mt]);
                uint32_t hoff = hbase + (uint32_t)(cbase + cs) * 32;
                ldm4(bhi, hh_hi_a + hoff);
                ldm4(blo, hh_lo_a + hoff);
#pragma unroll
                for (int mt = 0; mt < 2; mt++)
#pragma unroll
                    for (int n8 = 0; n8 < 2; n8++) {
                        mma_f16(acc[mt][n8], aw[mt], &bhi[n8 * 2]);
                        mma_f16(acc[mt][n8], aw[mt], &blo[n8 * 2]);
                    }
            }
            __syncthreads();
            if (sc < 3) {
                stage_SW(sc + 2, sc & 1);
                CP_COMMIT();
            }
        }

        // epilogue: acc -> ghs with bias
#pragma unroll
        for (int mt = 0; mt < 2; mt++) {
            int gate = mb + mt * 16 + (lane >> 2);
#pragma unroll
            for (int n8 = 0; n8 < 2; n8++) {
                int col = n8 * 8 + (lane & 3) * 2;
                ghs[col * GHS_PITCH + gate]           = acc[mt][n8][0] + bias_r[mt * 2];
                ghs[(col + 1) * GHS_PITCH + gate]     = acc[mt][n8][1] + bias_r[mt * 2];
                ghs[col * GHS_PITCH + gate + 8]       = acc[mt][n8][2] + bias_r[mt * 2 + 1];
                ghs[(col + 1) * GHS_PITCH + gate + 8] = acc[mt][n8][3] + bias_r[mt * 2 + 1];
            }
        }
        __syncthreads();

        // phase B
        size_t soff = (size_t)s * KP_SENT;
#pragma unroll
        for (int i = 0; i < 5; i++) {
            if (i < nB) {
                float gr = ghs[gho[i]];
                float gz = ghs[gho[i] + 200];
                float gn = ghs[gho[i] + 400];
                float xr = pg[pgo[i]];
                float xz = pg[pgo[i] + 200];
                float xn = pg[pgo[i] + 400];
                float rg = 1.f / (1.f + __expf(-(xr + gr)));
                float zg = 1.f / (1.f + __expf(-(xz + gz)));
                float nn = tanhf(xn + rg * gn);
                float hprev = hs[hso[i]];
                float hnew = (1.f - zg) * nn + zg * hprev;
                hs[hso[i]] = hnew;
                __half hb = __float2half_rn(hnew);
                __half hl = __float2half_rn(hnew - __half2float(hb));
                hh_hi[hho[i]] = hb;
                hh_lo[hho[i]] = hl;
                if (bvalid[i]) {
                    size_t o = obase[i] + soff;
                    Hhi[o] = hb;
                    Hlo[o] = hl;
                }
            }
        }
        __syncthreads();
    }
}

// ---------------- avg over sequence ----------------
__global__ void avg_kernel(const float* __restrict__ sent, const int* __restrict__ length,
                           float* __restrict__ avg) {
    int i = blockIdx.x * blockDim.x + threadIdx.x;
    if (i < B_ * H_) {
        int b = i / H_, h = i % H_;
        float s = 0.f;
        for (int t = 0; t < S_; t++) s += sent[((size_t)(b * S_ + t)) * H_ + h];
        avg[i] = s / (float)length[b];
    }
}

// ---------------- novelty scan + fused base (148 blocks x 7 rows) --------------
__global__ void __launch_bounds__(256, 1)
nov_kernel(const float* __restrict__ sent, const float4* __restrict__ Wnq,
           const float* __restrict__ bnov,
           const float* __restrict__ wcont, const float* __restrict__ doc,
           const int* __restrict__ apos, const int* __restrict__ rpos,
           const float* __restrict__ apos_table, const float* __restrict__ rpos_table,
           const float* __restrict__ apos_w, const float* __restrict__ rpos_w,
           const float* __restrict__ apos_b, const float* __restrict__ rpos_b,
           const float* __restrict__ bcont, const float* __restrict__ bias,
           float* __restrict__ out) {
    __shared__ float sum_s[NOV_ROWS * 200];
    __shared__ float st2[2][NOV_ROWS * 200];
    __shared__ float ps[NOV_ROWS * 200];
    __shared__ float wd[NOV_ROWS * 200];
    __shared__ float gsig[8];
    __shared__ float s_scal;
    int tid = threadIdx.x;
    int b0 = blockIdx.x * NOV_ROWS;
    uint32_t st_addr = smem_u32(st2);
    if (tid == 0) s_scal = *bcont + *apos_b + *rpos_b + *bias;
    for (int i = tid; i < NOV_ROWS * 200; i += 256) {
        int r = i / 200, j = i % 200;
        int b = b0 + r; if (b >= B_) b = B_ - 1;
        sum_s[i] = 0.f;
        wd[i] = wcont[j] + doc[(size_t)b * 200 + j];
    }
    auto stage_st = [&](int t, int buf) {
        for (int q = tid; q < NOV_ROWS * 50; q += 256) {
            int r = q / 50, c = q - r * 50;
            int b = b0 + r; if (b >= B_) b = B_ - 1;
            const float* src = sent + (size_t)(b * S_ + t) * 200 + c * 4;
            CP_ASYNC16(st_addr + (uint32_t)(buf * NOV_ROWS * 200 + r * 200 + c * 4) * 4, src);
        }
        CP_COMMIT();
    };
    stage_st(0, 0);
    int cur = 0;
    for (int t = 0; t < S_; t++) {
        if (t + 1 < S_) {
            stage_st(t + 1, cur ^ 1);
            CP_WAIT1();
        } else {
            CP_WAIT0();
        }
        __syncthreads();
        const float* st = st2[cur];
        if (tid < 200) {
            float2 acc2[NOV_ROWS];
#pragma unroll
            for (int r = 0; r < NOV_ROWS; r++) acc2[r] = make_float2(0.f, 0.f);
            for (int k4 = 0; k4 < 50; k4++) {
                float4 w = Wnq[k4 * 200 + tid];
                float2 w01 = make_float2(w.x, w.y);
                float2 w23 = make_float2(w.z, w.w);
#pragma unroll
                for (int r = 0; r < NOV_ROWS; r++) {
                    float4 h4 = *(const float4*)&st[r * 200 + k4 * 4];
                    acc2[r] = ffma2(w01, make_float2(h4.x, h4.y), acc2[r]);
                    acc2[r] = ffma2(w23, make_float2(h4.z, h4.w), acc2[r]);
                }
            }
            float bb = bnov[tid];
#pragma unroll
            for (int r = 0; r < NOV_ROWS; r++)
                ps[r * 200 + tid] = (acc2[r].x + acc2[r].y + bb) * tanhf(sum_s[r * 200 + tid]);
        }
        __syncthreads();
        int w = tid >> 5, lane = tid & 31;
        if (w < NOV_ROWS) {
            int b = b0 + w; if (b >= B_) b = B_ - 1;
            float acc = 0.f;
            for (int j = lane; j < 200; j += 32)
                acc += st[w * 200 + j] * wd[w * 200 + j] - ps[w * 200 + j];
            int ap = apos[b * S_ + t]; ap = ap < 0 ? 0 : (ap > 50 ? 50 : ap);
            int rp = rpos[b * S_ + t]; rp = rp < 0 ? 0 : (rp > 4 ? 4 : rp);
            for (int p = lane; p < 50; p += 32)
                acc += apos_table[ap * 50 + p] * apos_w[p] + rpos_table[rp * 50 + p] * rpos_w[p];
            for (int off = 16; off; off >>= 1) acc += __shfl_down_sync(0xffffffffu, acc, off);
            if (lane == 0) {
                float logit = acc + s_scal;
                if (b0 + w < B_) out[(size_t)(b0 + w) * S_ + t] = logit;
                gsig[w] = 1.f / (1.f + __expf(-logit));
            }
        }
        __syncthreads();
        for (int i = tid; i < NOV_ROWS * 200; i += 256) {
            int r = i / 200;
            sum_s[i] += st[i] * gsig[r];
        }
        __syncthreads();
        cur ^= 1;
    }
}

// ---------------- host launch ----------------
static float* sym_addr(const void* sym) {
    void* p = nullptr;
    cudaGetSymbolAddress(&p, sym);
    return (float*)p;
}

extern "C" void kernel_launch(void* const* d_in, const int* in_sizes, int n_in,
                              void* d_out, int out_size) {
    const float* seq        = (const float*)d_in[0];
    const int*   apos       = (const int*)d_in[1];
    const int*   rpos       = (const int*)d_in[2];
    const int*   length     = (const int*)d_in[3];
    const float* apos_table = (const float*)d_in[4];
    const float* rpos_table = (const float*)d_in[5];
    const float* apos_w     = (const float*)d_in[6];
    const float* apos_b     = (const float*)d_in[7];
    const float* rpos_w     = (const float*)d_in[8];
    const float* rpos_b     = (const float*)d_in[9];
    const float* Wih_f      = (const float*)d_in[10];
    const float* Whh_f      = (const float*)d_in[11];
    const float* bih_f      = (const float*)d_in[12];
    const float* bhh_f      = (const float*)d_in[13];
    const float* Wih_b      = (const float*)d_in[14];
    const float* Whh_b      = (const float*)d_in[15];
    const float* bih_b      = (const float*)d_in[16];
    const float* bhh_b      = (const float*)d_in[17];
    const float* Wsent      = (const float*)d_in[18];
    const float* bsent      = (const float*)d_in[19];
    const float* wcont      = (const float*)d_in[20];
    const float* bcont      = (const float*)d_in[21];
    const float* Wdoc1      = (const float*)d_in[22];
    const float* bdoc1      = (const float*)d_in[23];
    const float* Wdoc2      = (const float*)d_in[24];
    const float* bdoc2      = (const float*)d_in[25];
    const float* Wnov       = (const float*)d_in[26];
    const float* bnov       = (const float*)d_in[27];
    const float* bias       = (const float*)d_in[28];
    float* out = (float*)d_out;

    float* gx     = sym_addr(g_gx);
    float* sent   = sym_addr(g_sent);
    float* avg    = sym_addr(g_avg);
    float* tmp    = sym_addr(g_tmp);
    float* doc    = sym_addr(g_doc);
    float4* wnq   = (float4*)sym_addr(g_Wnq);
    __half* Wc  = (__half*)sym_addr(g_Wc);
    __half* Ahi = (__half*)sym_addr(g_Ahi);
    __half* Alo = (__half*)sym_addr(g_Alo);
    __half* Hhi = (__half*)sym_addr(g_Hhi);
    __half* Hlo = (__half*)sym_addr(g_Hlo);
    __half* Bgx = (__half*)sym_addr(g_Bgx);
    __half* Bse = (__half*)sym_addr(g_Bse);

    cudaFuncSetAttribute(mma_gemm<0>, cudaFuncAttributeMaxDynamicSharedMemorySize, MMA_SMEM);
    cudaFuncSetAttribute(mma_gemm<1>, cudaFuncAttributeMaxDynamicSharedMemorySize, MMA_SMEM);
    cudaFuncSetAttribute(gru_kernel, cudaFuncAttributeMaxDynamicSharedMemorySize, GRU_SMEM);

    // launch 1: weight packs
    pack_all<<<(2 * NCHUNK * GATES * 16 + 10000 + 255) / 256, 256>>>(
        Whh_f, Whh_b, Wnov, Wc, wnq);
    // launch 2: gx-side conversions
    conv_prep<<<1600 + (int)(((size_t)M_ * KP_GX + 255) / 256), 256>>>(
        Wih_f, Wih_b, seq, Bgx, Ahi, Alo);
    // launch 3: combined gx GEMM
    mma_gemm<0><<<dim3(NP_GX / 128, M_ / 128), 256, MMA_SMEM>>>(
        Ahi, Alo, Bgx, bih_f, bih_b, 600, gx, NGX, NGX, KP_GX);
    // launch 4 (profiled): tensor-core GRU
    gru_kernel<<<dim3(74, 2), 608, GRU_SMEM>>>(
        gx, Wc, bhh_f, bhh_b, Hhi, Hlo);

    // sent-weight conversion + sent GEMM
    conv_f16<<<((size_t)NP_SENT * KP_SENT + 255) / 256, 256>>>(
        Wsent, 200, 2 * H_, KP_SENT, NP_SENT, Bse);
    mma_gemm<1><<<dim3(NP_SENT / 128, M_ / 128), 256, MMA_SMEM>>>(
        Hhi, Hlo, Bse, bsent, bsent, H_, sent, H_, H_, KP_SENT);

    // avg + doc MLP
    avg_kernel<<<(B_ * H_ + 255) / 256, 256>>>(sent, length, avg);
    sgemm_nt<2><<<dim3(2, 8), 256>>>(avg, Wdoc1, bdoc1, tmp, B_, H_, H_);
    sgemm_nt<0><<<dim3(2, 8), 256>>>(tmp, Wdoc2, bdoc2, doc, B_, H_, H_);

    // novelty scan + fused base -> output
    nov_kernel<<<148, 256>>>(sent, wnq, bnov, wcont, doc, apos, rpos,
                             apos_table, rpos_table, apos_w, rpos_w,
                             apos_b, rpos_b, bcont, bias, out);
}

// round 16
// speedup vs baseline: 2.2964x; 1.1341x over previous
#include <cuda_runtime.h>
#include <cuda_fp16.h>
#include <math.h>
#include <stdint.h>

#define B_   1024
#define S_   50
#define E_   300
#define H_   200
#define M_   51200
#define NGX  1200
#define KP_GX   320
#define KP_SENT 416
#define NP_GX   1280
#define NP_SENT 256
#define GRU_ROWS 14
#define NOV_ROWS 7
#define GATES 608
#define NCHUNK 13
#define WCH_BYTES (GATES * 16 * 2)      // 19456 B per k16 chunk
#define SWBUF_BYTES (3 * WCH_BYTES)     // 58368 B per super-chunk buffer
#define HH_PITCH 216
#define GHS_PITCH 612
// nov tensor-core constants
#define NGATE 208                        // 200 padded to 13 m16 tiles
#define NKCH 13
#define WNCH_BYTES (NGATE * 32)          // 6656 B per k16 chunk (32B rows, swizzled)
#define WN_TOTAL (NKCH * NGATE * 16)     // 43264 halves
#define ST_PITCH 216                     // halves
#define PS_PITCH 212                     // floats

// ---------------- scratch (device globals; no allocations) ----------------
__device__ __align__(256) __half g_Ahi[(size_t)M_ * KP_GX];
__device__ __align__(256) __half g_Alo[(size_t)M_ * KP_GX];
__device__ __align__(256) __half g_Hhi[(size_t)M_ * KP_SENT];
__device__ __align__(256) __half g_Hlo[(size_t)M_ * KP_SENT];
__device__ __align__(256) __half g_Bgx[(size_t)NP_GX * KP_GX];
__device__ __align__(256) __half g_Bse[(size_t)NP_SENT * KP_SENT];
__device__ __align__(256) __half g_Wc[2 * NCHUNK * GATES * 16];
__device__ __align__(256) __half g_Wnhi[WN_TOTAL];
__device__ __align__(256) __half g_Wnlo[WN_TOTAL];
__device__ __align__(256) float g_gx[(size_t)M_ * NGX];
__device__ __align__(256) float g_sent[(size_t)M_ * H_];
__device__ float g_avg[B_ * H_];
__device__ float g_tmp[B_ * H_];
__device__ float g_doc[B_ * H_];

// ---------------- helpers ----------------
__device__ __forceinline__ uint32_t smem_u32(const void* p) {
    uint32_t a;
    asm("{ .reg .u64 t; cvta.to.shared.u64 t, %1; cvt.u32.u64 %0, t; }" : "=r"(a) : "l"(p));
    return a;
}
__device__ __forceinline__ void ldm4(uint32_t* r, uint32_t addr) {
    asm volatile("ldmatrix.sync.aligned.m8n8.x4.shared.b16 {%0,%1,%2,%3}, [%4];"
        : "=r"(r[0]), "=r"(r[1]), "=r"(r[2]), "=r"(r[3]) : "r"(addr));
}
__device__ __forceinline__ void mma_f16(float* c, const uint32_t* a, const uint32_t* b) {
    asm volatile(
        "mma.sync.aligned.m16n8k16.row.col.f32.f16.f16.f32 "
        "{%0,%1,%2,%3}, {%4,%5,%6,%7}, {%8,%9}, {%0,%1,%2,%3};"
        : "+f"(c[0]), "+f"(c[1]), "+f"(c[2]), "+f"(c[3])
        : "r"(a[0]), "r"(a[1]), "r"(a[2]), "r"(a[3]), "r"(b[0]), "r"(b[1]));
}
__device__ __forceinline__ float2 ffma2(float2 a, float2 b, float2 c) {
    unsigned long long ua = *(unsigned long long*)&a;
    unsigned long long ub = *(unsigned long long*)&b;
    unsigned long long uc = *(unsigned long long*)&c;
    unsigned long long r;
    asm("fma.rn.f32x2 %0, %1, %2, %3;" : "=l"(r) : "l"(ua), "l"(ub), "l"(uc));
    return *(float2*)&r;
}
#define CP_ASYNC16(dst, src) \
    asm volatile("cp.async.cg.shared.global [%0], [%1], 16;" :: "r"(dst), "l"(src))
#define CP_COMMIT() asm volatile("cp.async.commit_group;")
#define CP_WAIT0() asm volatile("cp.async.wait_group 0;")
#define CP_WAIT1() asm volatile("cp.async.wait_group 1;")

// ---------------- weight packs: Whh fp16 chunks + Wnov hi/lo chunks ----------
__global__ void pack_all(const float* __restrict__ Whh_f, const float* __restrict__ Whh_b,
                         const float* __restrict__ Wnov,
                         __half* __restrict__ Wc,
                         __half* __restrict__ Wnhi, __half* __restrict__ Wnlo) {
    int i = blockIdx.x * blockDim.x + threadIdx.x;
    const int WC_TOTAL = 2 * NCHUNK * GATES * 16;
    if (i < WC_TOTAL) {
        int kk = i & 15;
        int t = i >> 4;
        int g = t % GATES; t /= GATES;
        int c = t % NCHUNK;
        int dir = t / NCHUNK;
        const float* W = dir ? Whh_b : Whh_f;
        int k = c * 16 + kk;
        float v = (g < 600 && k < 200) ? W[(size_t)g * 200 + k] : 0.f;
        Wc[i] = __float2half_rn(v);
    } else if (i < WC_TOTAL + WN_TOTAL) {
        int idx = i - WC_TOTAL;
        int kk = idx & 15;
        int t = idx >> 4;
        int g = t % NGATE;
        int c = t / NGATE;
        int k = c * 16 + kk;
        float v = (g < 200 && k < 200) ? Wnov[(size_t)g * 200 + k] : 0.f;
        __half h = __float2half_rn(v);
        Wnhi[idx] = h;
        Wnlo[idx] = __float2half_rn(v - __half2float(h));
    }
}

// ---------------- combined gx-side fp16 conversion ----------------
__global__ void conv_prep(const float* __restrict__ Wih_f, const float* __restrict__ Wih_b,
                          const float* __restrict__ seq,
                          __half* __restrict__ Bgx,
                          __half* __restrict__ Ahi, __half* __restrict__ Alo) {
    if (blockIdx.x < 1600) {
        int i = blockIdx.x * 256 + threadIdx.x;
        if (i >= NP_GX * KP_GX) return;
        int row = i / KP_GX, k = i - row * KP_GX;
        float x = 0.f;
        if (k < E_) {
            if (row < 600) x = Wih_f[(size_t)row * E_ + k];
            else if (row < 1200) x = Wih_b[(size_t)(row - 600) * E_ + k];
        }
        Bgx[i] = __float2half_rn(x);
    } else {
        size_t i = (size_t)(blockIdx.x - 1600) * 256 + threadIdx.x;
        if (i >= (size_t)M_ * KP_GX) return;
        int row = (int)(i / KP_GX), k = (int)(i - (size_t)row * KP_GX);
        float x = (k < E_) ? seq[(size_t)row * E_ + k] : 0.f;
        __half h = __float2half_rn(x);
        Ahi[i] = h;
        Alo[i] = __float2half_rn(x - __half2float(h));
    }
}

// ---------------- generic fp32 -> fp16 conversion (sent weights) --------------
__global__ void conv_f16(const float* __restrict__ X0,
                         int rows0, int K, int Kpad, int totalRows,
                         __half* __restrict__ hi) {
    int i = blockIdx.x * blockDim.x + threadIdx.x;
    if (i >= totalRows * Kpad) return;
    int row = i / Kpad, k = i - row * Kpad;
    float x = (k < K && row < rows0) ? X0[(size_t)row * K + k] : 0.f;
    hi[i] = __float2half_rn(x);
}

// ---------------- 2-pass split-fp16 tensor-core GEMM (mma.sync) ----------------
#define NSTAGE 3
#define STAGE_BYTES 30720
#define MMA_SMEM (NSTAGE * STAGE_BYTES)

template <int ACT>
__global__ void __launch_bounds__(256, 2)
mma_gemm(const __half* __restrict__ Ahi, const __half* __restrict__ Alo,
         const __half* __restrict__ Bm,
         const float* __restrict__ bias0, const float* __restrict__ bias1, int nsplit,
         float* __restrict__ C, int ldc, int Nvalid, int Kpad) {
    extern __shared__ __align__(16) __half smbuf[];
    uint32_t sb = smem_u32(smbuf);
    int tid = threadIdx.x;
    int w = tid >> 5, lane = tid & 31;
    int wm = (w >> 1) * 32, wn = (w & 1) * 64;
    int m0 = blockIdx.y * 128, n0 = blockIdx.x * 128;

    const __half* gsrc0 = Ahi + (size_t)m0 * Kpad;
    const __half* gsrc1 = Alo + (size_t)m0 * Kpad;
    const __half* gsrc2 = Bm + (size_t)n0 * Kpad;

    float acc[2][8][4];
#pragma unroll
    for (int i = 0; i < 2; i++)
#pragma unroll
        for (int j = 0; j < 8; j++)
#pragma unroll
            for (int e = 0; e < 4; e++) acc[i][j][e] = 0.f;

    int rowA = ((lane >> 3) & 1) * 8 + (lane & 7);
    int kA   = ((lane >> 4) & 1) * 8;
    int rowB = ((lane >> 4) & 1) * 8 + (lane & 7);
    int kB   = ((lane >> 3) & 1) * 8;

    int nst = Kpad / 32;
    auto load_stage = [&](int s) {
        int buf = s % NSTAGE;
        int k0 = s * 32;
#pragma unroll
        for (int i = 0; i < 6; i++) {
            int t = tid + i * 256;
            int mat = t >> 9;
            int c = t & 511;
            int row = c >> 2, kc = c & 3;
            uint32_t dst = sb + buf * STAGE_BYTES + mat * 10240 + row * 80 + kc * 16;
            const __half* src =
                (mat == 0 ? gsrc0 : mat == 1 ? gsrc1 : gsrc2)
                + (size_t)row * Kpad + k0 + kc * 8;
            CP_ASYNC16(dst, src);
        }
        CP_COMMIT();
    };

    load_stage(0);
    if (nst > 1) load_stage(1);
    for (int s = 0; s < nst; s++) {
        if (s + 2 < nst) {
            load_stage(s + 2);
            asm volatile("cp.async.wait_group 2;");
        } else if (s + 1 < nst) {
            CP_WAIT1();
        } else {
            CP_WAIT0();
        }
        __syncthreads();
        uint32_t base = sb + (s % NSTAGE) * STAGE_BYTES;
#pragma unroll
        for (int k16 = 0; k16 < 32; k16 += 16) {
            uint32_t ah[2][4], al[2][4];
#pragma unroll
            for (int ma = 0; ma < 2; ma++) {
                uint32_t off = (uint32_t)(((wm + ma * 16 + rowA) * 40 + k16 + kA) * 2);
                ldm4(ah[ma], base + off);
                ldm4(al[ma], base + 10240 + off);
            }
            uint32_t bh[4][4];
#pragma unroll
            for (int nb = 0; nb < 4; nb++) {
                uint32_t off = (uint32_t)(((wn + nb * 16 + rowB) * 40 + k16 + kB) * 2);
                ldm4(bh[nb], base + 20480 + off);
            }
#pragma unroll
            for (int ma = 0; ma < 2; ma++)
#pragma unroll
                for (int na = 0; na < 8; na++)
                    mma_f16(acc[ma][na], ah[ma], &bh[na >> 1][(na & 1) * 2]);
#pragma unroll
            for (int ma = 0; ma < 2; ma++)
#pragma unroll
                for (int na = 0; na < 8; na++)
                    mma_f16(acc[ma][na], al[ma], &bh[na >> 1][(na & 1) * 2]);
        }
        __syncthreads();
    }

    int r0 = m0 + wm + (lane >> 2);
    int cb = n0 + wn + (lane & 3) * 2;
#pragma unroll
    for (int ma = 0; ma < 2; ma++) {
        int r = r0 + ma * 16;
#pragma unroll
        for (int na = 0; na < 8; na++) {
            int col = cb + na * 8;
            if (col < Nvalid) {
                float b0v = (col < nsplit) ? bias0[col] : bias1[col - nsplit];
                float b1v = (col + 1 < nsplit) ? bias0[col + 1] : bias1[col + 1 - nsplit];
                float2 v0 = make_float2(acc[ma][na][0] + b0v, acc[ma][na][1] + b1v);
                float2 v1 = make_float2(acc[ma][na][2] + b0v, acc[ma][na][3] + b1v);
                if (ACT == 1) {
                    v0.x = fmaxf(v0.x, 0.f); v0.y = fmaxf(v0.y, 0.f);
                    v1.x = fmaxf(v1.x, 0.f); v1.y = fmaxf(v1.y, 0.f);
                }
                *(float2*)&C[(size_t)r * ldc + col] = v0;
                *(float2*)&C[(size_t)(r + 8) * ldc + col] = v1;
            }
        }
    }
}

// ---------------- small fp32 SGEMM (doc MLP only) ----------------
template <int ACT>
__global__ void __launch_bounds__(256, 2)
sgemm_nt(const float* __restrict__ A, const float* __restrict__ Bm,
         const float* __restrict__ bias, float* __restrict__ C,
         int M, int N, int K) {
    __shared__ float As[2][8][128];
    __shared__ float Bs[2][8][128];
    int tid = threadIdx.x;
    int tx = tid & 15, ty = tid >> 4;
    int m0 = blockIdx.y * 128, n0 = blockIdx.x * 128;
    int lr = tid >> 1, lq = tid & 1;
    int m = m0 + lr, n = n0 + lr;
    bool nok = (n < N);
    const float* Arow = A + (size_t)m * K;
    const float* Brow = Bm + (size_t)n * K;
    float2 acc[8][4];
#pragma unroll
    for (int i = 0; i < 8; i++)
#pragma unroll
        for (int j = 0; j < 4; j++) acc[i][j] = make_float2(0.f, 0.f);
    float av[4], bv[4];
    auto load_chunk = [&](int k0) {
        int k = k0 + lq * 4;
#pragma unroll
        for (int i = 0; i < 4; i++) {
            av[i] = (k + i < K) ? Arow[k + i] : 0.f;
            bv[i] = (nok && k + i < K) ? Brow[k + i] : 0.f;
        }
    };
    auto store_chunk = [&](int buf) {
#pragma unroll
        for (int i = 0; i < 4; i++) {
            As[buf][lq * 4 + i][lr] = av[i];
            Bs[buf][lq * 4 + i][lr] = bv[i];
        }
    };
    auto compute = [&](int buf) {
#pragma unroll
        for (int kk = 0; kk < 8; kk++) {
            float4 a0 = *(const float4*)&As[buf][kk][ty * 8];
            float4 a1 = *(const float4*)&As[buf][kk][ty * 8 + 4];
            float4 b0 = *(const float4*)&Bs[buf][kk][tx * 8];
            float4 b1 = *(const float4*)&Bs[buf][kk][tx * 8 + 4];
            float a[8] = {a0.x, a0.y, a0.z, a0.w, a1.x, a1.y, a1.z, a1.w};
            float2 b2[4] = {make_float2(b0.x, b0.y), make_float2(b0.z, b0.w),
                            make_float2(b1.x, b1.y), make_float2(b1.z, b1.w)};
#pragma unroll
            for (int i = 0; i < 8; i++) {
                float2 ad = make_float2(a[i], a[i]);
#pragma unroll
                for (int j = 0; j < 4; j++) acc[i][j] = ffma2(ad, b2[j], acc[i][j]);
            }
        }
    };
    int nt = (K + 7) / 8;
    load_chunk(0);
    store_chunk(0);
    __syncthreads();
    int cur = 0;
    for (int t = 1; t < nt; t++) {
        load_chunk(t * 8);
        compute(cur);
        store_chunk(cur ^ 1);
        __syncthreads();
        cur ^= 1;
    }
    compute(cur);
#pragma unroll
    for (int i = 0; i < 8; i++) {
        int mm = m0 + ty * 8 + i;
#pragma unroll
        for (int j = 0; j < 4; j++) {
            int nn = n0 + tx * 8 + j * 2;
            if (nn + 1 < N) {
                float2 v = acc[i][j];
                if (bias) { v.x += bias[nn]; v.y += bias[nn + 1]; }
                if (ACT == 1) { v.x = fmaxf(v.x, 0.f); v.y = fmaxf(v.y, 0.f); }
                if (ACT == 2) { v.x = tanhf(v.x); v.y = tanhf(v.y); }
                *(float2*)&C[(size_t)mm * N + nn] = v;
            } else if (nn < N) {
                float v = acc[i][j].x + (bias ? bias[nn] : 0.f);
                if (ACT == 1) v = fmaxf(v, 0.f);
                if (ACT == 2) v = tanhf(v);
                C[(size_t)mm * N + nn] = v;
            }
        }
    }
}

// ---------------- tensor-core GRU recurrence (persistent, 148 blocks) ----------
#define GRU_SMEM 214528
__global__ void __launch_bounds__(608, 1)
gru_kernel(const float* __restrict__ gx, const __half* __restrict__ Wc,
           const float* __restrict__ bhhf, const float* __restrict__ bhhb,
           __half* __restrict__ Hhi, __half* __restrict__ Hlo) {
    extern __shared__ float sm[];
    float* hs   = sm;
    float* ghs  = sm + 2800;
    float* pg   = sm + 12592;
    __half* hh_hi = (__half*)(sm + 20992);
    __half* hh_lo = hh_hi + 16 * HH_PITCH;
    uint32_t pg_addr = smem_u32(pg);
    uint32_t hh_hi_a = smem_u32(hh_hi);
    uint32_t hh_lo_a = smem_u32(hh_lo);
    uint32_t wb_a    = smem_u32(sm + 24448);

    int dir = blockIdx.y;
    const float* bhh = dir ? bhhb : bhhf;
    const __half* WcD = Wc + (size_t)dir * NCHUNK * GATES * 16;
    int b0 = blockIdx.x * GRU_ROWS;
    int tid = threadIdx.x;
    int wid = tid >> 5, lane = tid & 31;
    int mb = wid * 32;

    int rowA = ((lane >> 3) & 1) * 8 + (lane & 7);
    int kA   = ((lane >> 4) & 1) * 8;
    int rowB = ((lane >> 4) & 1) * 8 + (lane & 7);
    int kB   = ((lane >> 3) & 1) * 8;
    int kpartA = kA >> 3;

    uint32_t awoff[2];
#pragma unroll
    for (int mt = 0; mt < 2; mt++) {
        int rg = mb + mt * 16 + rowA;
        int psw = kpartA ^ ((rg >> 2) & 1);
        awoff[mt] = (uint32_t)(rg * 32 + psw * 16);
    }
    uint32_t hbase = (uint32_t)(rowB * HH_PITCH + kB) * 2;

    int row_a = tid >> 1, part_a = tid & 1;
    uint32_t wsrcA = (uint32_t)(row_a * 16 + part_a * 8);
    uint32_t wdstA = (uint32_t)(row_a * 32 + ((part_a ^ ((row_a >> 2) & 1)) * 16));
    uint32_t wsrcB = wsrcA + 304 * 16;
    uint32_t wdstB = wdstA + 304 * 32;

    int nG = 0;
    int growb[4]; int gcol[4]; uint32_t gdst[4];
    for (int q = tid; q < GRU_ROWS * 150; q += 608) {
        int r = q / 150, c = q - r * 150;
        int b = b0 + r;
        int bc = b < B_ ? b : B_ - 1;
        growb[nG] = bc * S_;
        gcol[nG] = dir * 600 + c * 4;
        gdst[nG] = pg_addr + (uint32_t)(r * 600 + c * 4) * 4;
        nG++;
    }

    int nB = 0;
    int pgo[5], gho[5], hso[5], hho[5], bvalid[5];
    size_t obase[5];
    for (int idx = tid; idx < GRU_ROWS * 200; idx += 608) {
        int r = idx / 200, j = idx - r * 200;
        int b = b0 + r;
        pgo[nB] = r * 600 + j;
        gho[nB] = r * GHS_PITCH + j;
        hso[nB] = idx;
        hho[nB] = r * HH_PITCH + j;
        bvalid[nB] = (b < B_);
        obase[nB] = (size_t)(b < B_ ? b : 0) * S_ * KP_SENT + dir * 200 + j;
        nB++;
    }

    float bias_r[4];
#pragma unroll
    for (int q = 0; q < 4; q++) {
        int g = mb + q * 8 + (lane >> 2);
        bias_r[q] = (g < 600) ? bhh[g] : 0.f;
    }

    for (int i = tid; i < 2800; i += 608) hs[i] = 0.f;
    for (int i = tid; i < 16 * HH_PITCH; i += 608) { hh_hi[i] = __half(0.f); hh_lo[i] = __half(0.f); }
    __syncthreads();

    auto stage_SW = [&](int sc, int buf) {
        int cnt = (sc == 4) ? 1 : 3;
        uint32_t dbase = wb_a + buf * SWBUF_BYTES;
        const __half* sbase = WcD + (size_t)(3 * sc) * GATES * 16;
        for (int cs = 0; cs < cnt; cs++) {
            CP_ASYNC16(dbase + cs * WCH_BYTES + wdstA, sbase + cs * GATES * 16 + wsrcA);
            CP_ASYNC16(dbase + cs * WCH_BYTES + wdstB, sbase + cs * GATES * 16 + wsrcB);
        }
    };

    for (int t = 0; t < S_; t++) {
        int s = dir ? (S_ - 1 - t) : t;
#pragma unroll
        for (int i = 0; i < 4; i++) {
            if (i < nG) {
                const float* src = gx + (size_t)(growb[i] + s) * NGX + gcol[i];
                CP_ASYNC16(gdst[i], src);
            }
        }
        stage_SW(0, 0);
        CP_COMMIT();
        stage_SW(1, 1);
        CP_COMMIT();

        float acc[2][2][4];
#pragma unroll
        for (int i = 0; i < 2; i++)
#pragma unroll
            for (int j = 0; j < 2; j++)
#pragma unroll
                for (int e = 0; e < 4; e++) acc[i][j][e] = 0.f;

        for (int sc = 0; sc < 5; sc++) {
            if (sc < 4) CP_WAIT1(); else CP_WAIT0();
            __syncthreads();
            uint32_t wb = wb_a + (sc & 1) * SWBUF_BYTES;
            int cnt = (sc == 4) ? 1 : 3;
            int cbase = 3 * sc;
            for (int cs = 0; cs < cnt; cs++) {
                uint32_t aw[2][4], bhi[4], blo[4];
#pragma unroll
                for (int mt = 0; mt < 2; mt++)
                    ldm4(aw[mt], wb + cs * WCH_BYTES + awoff[mt]);
                uint32_t hoff = hbase + (uint32_t)(cbase + cs) * 32;
                ldm4(bhi, hh_hi_a + hoff);
                ldm4(blo, hh_lo_a + hoff);
#pragma unroll
                for (int mt = 0; mt < 2; mt++)
#pragma unroll
                    for (int n8 = 0; n8 < 2; n8++) {
                        mma_f16(acc[mt][n8], aw[mt], &bhi[n8 * 2]);
                        mma_f16(acc[mt][n8], aw[mt], &blo[n8 * 2]);
                    }
            }
            __syncthreads();
            if (sc < 3) {
                stage_SW(sc + 2, sc & 1);
                CP_COMMIT();
            }
        }

#pragma unroll
        for (int mt = 0; mt < 2; mt++) {
            int gate = mb + mt * 16 + (lane >> 2);
#pragma unroll
            for (int n8 = 0; n8 < 2; n8++) {
                int col = n8 * 8 + (lane & 3) * 2;
                ghs[col * GHS_PITCH + gate]           = acc[mt][n8][0] + bias_r[mt * 2];
                ghs[(col + 1) * GHS_PITCH + gate]     = acc[mt][n8][1] + bias_r[mt * 2];
                ghs[col * GHS_PITCH + gate + 8]       = acc[mt][n8][2] + bias_r[mt * 2 + 1];
                ghs[(col + 1) * GHS_PITCH + gate + 8] = acc[mt][n8][3] + bias_r[mt * 2 + 1];
            }
        }
        __syncthreads();

        size_t soff = (size_t)s * KP_SENT;
#pragma unroll
        for (int i = 0; i < 5; i++) {
            if (i < nB) {
                float gr = ghs[gho[i]];
                float gz = ghs[gho[i] + 200];
                float gn = ghs[gho[i] + 400];
                float xr = pg[pgo[i]];
                float xz = pg[pgo[i] + 200];
                float xn = pg[pgo[i] + 400];
                float rg = 1.f / (1.f + __expf(-(xr + gr)));
                float zg = 1.f / (1.f + __expf(-(xz + gz)));
                float nn = tanhf(xn + rg * gn);
                float hprev = hs[hso[i]];
                float hnew = (1.f - zg) * nn + zg * hprev;
                hs[hso[i]] = hnew;
                __half hb = __float2half_rn(hnew);
                __half hl = __float2half_rn(hnew - __half2float(hb));
                hh_hi[hho[i]] = hb;
                hh_lo[hho[i]] = hl;
                if (bvalid[i]) {
                    size_t o = obase[i] + soff;
                    Hhi[o] = hb;
                    Hlo[o] = hl;
                }
            }
        }
        __syncthreads();
    }
}

// ---------------- avg over sequence ----------------
__global__ void avg_kernel(const float* __restrict__ sent, const int* __restrict__ length,
                           float* __restrict__ avg) {
    int i = blockIdx.x * blockDim.x + threadIdx.x;
    if (i < B_ * H_) {
        int b = i / H_, h = i % H_;
        float s = 0.f;
        for (int t = 0; t < S_; t++) s += sent[((size_t)(b * S_ + t)) * H_ + h];
        avg[i] = s / (float)length[b];
    }
}

// ---------------- tensor-core novelty scan + fused base (148 blocks) -----------
// Wnov hi/lo resident in smem (loaded once); per step: 13 chunks x 3 mma passes
// from resident operands. sent stays fp32 for the exact sum_s recurrence.
// smem: sum_s|wd|st2|ps|bnv|gsig+scal | sthi/stlo | Wnhi | Wnlo = 223680 B
#define NOV_SMEM 223680
__global__ void __launch_bounds__(256, 1)
nov_kernel(const float* __restrict__ sent,
           const __half* __restrict__ Wnhi, const __half* __restrict__ Wnlo,
           const float* __restrict__ bnov,
           const float* __restrict__ wcont, const float* __restrict__ doc,
           const int* __restrict__ apos, const int* __restrict__ rpos,
           const float* __restrict__ apos_table, const float* __restrict__ rpos_table,
           const float* __restrict__ apos_w, const float* __restrict__ rpos_w,
           const float* __restrict__ apos_b, const float* __restrict__ rpos_b,
           const float* __restrict__ bcont, const float* __restrict__ bias,
           float* __restrict__ out) {
    extern __shared__ float sm[];
    float* sum_s = sm;                  // 1400
    float* wd    = sm + 1400;           // 1400
    float* st2b  = sm + 2800;           // 2 x 1400
    float* ps    = sm + 5600;           // 16 x 212 = 3392
    float* bnv   = sm + 8992;           // 200
    float* gsig  = sm + 9192;           // 7 (+ s_scal at sm[9199])
    __half* sthi = (__half*)(sm + 9200);           // 16 x 216
    __half* stlo = sthi + 16 * ST_PITCH;
    uint32_t st_addr  = smem_u32(st2b);
    uint32_t sthi_a   = smem_u32(sthi);
    uint32_t stlo_a   = smem_u32(stlo);
    uint32_t whi_a    = sthi_a + 2 * 16 * ST_PITCH * 2;   // after st tiles
    uint32_t wlo_a    = whi_a + NKCH * WNCH_BYTES;

    int tid = threadIdx.x;
    int b0 = blockIdx.x * NOV_ROWS;
    int wrp = tid >> 5, lane = tid & 31;
    int mt0 = 2 * wrp, mt1 = 2 * wrp + 1;   // m16 tiles of gates
    bool v0 = (mt0 < NKCH), v1 = (mt1 < NKCH);

    int rowA = ((lane >> 3) & 1) * 8 + (lane & 7);
    int kA   = ((lane >> 4) & 1) * 8;
    int rowB = ((lane >> 4) & 1) * 8 + (lane & 7);
    int kB   = ((lane >> 3) & 1) * 8;
    int kpartA = kA >> 3;

    uint32_t aw0 = 0, aw1 = 0;
    if (v0) { int rg = mt0 * 16 + rowA; aw0 = (uint32_t)(rg * 32 + ((kpartA ^ ((rg >> 2) & 1)) * 16)); }
    if (v1) { int rg = mt1 * 16 + rowA; aw1 = (uint32_t)(rg * 32 + ((kpartA ^ ((rg >> 2) & 1)) * 16)); }
    uint32_t hbase = (uint32_t)(rowB * ST_PITCH + kB) * 2;

    if (tid == 0) sm[9199] = *bcont + *apos_b + *rpos_b + *bias;
    for (int i = tid; i < 200; i += 256) bnv[i] = bnov[i];
    for (int i = tid; i < 1400; i += 256) {
        int r = i / 200, j = i % 200;
        int b = b0 + r; if (b >= B_) b = B_ - 1;
        sum_s[i] = 0.f;
        wd[i] = wcont[j] + doc[(size_t)b * 200 + j];
    }
    // zero st tile rows 7..15
    for (int i = tid; i < 16 * ST_PITCH; i += 256) {
        if (i / ST_PITCH >= NOV_ROWS || i % ST_PITCH >= 200) { sthi[i] = __half(0.f); stlo[i] = __half(0.f); }
    }
    // load resident Wnov hi/lo chunks (swizzled 32B rows)
    for (int q = tid; q < NKCH * NGATE * 2; q += 256) {
        int c = q / (NGATE * 2);
        int rem = q - c * (NGATE * 2);
        int g = rem >> 1, p = rem & 1;
        uint32_t doff = (uint32_t)(c * WNCH_BYTES + g * 32 + ((p ^ ((g >> 2) & 1)) * 16));
        const __half* sh = Wnhi + ((size_t)c * NGATE + g) * 16 + p * 8;
        const __half* sl = Wnlo + ((size_t)c * NGATE + g) * 16 + p * 8;
        CP_ASYNC16(whi_a + doff, sh);
        CP_ASYNC16(wlo_a + doff, sl);
    }
    CP_COMMIT();

    auto stage_st = [&](int t, int buf) {
        for (int q = tid; q < NOV_ROWS * 50; q += 256) {
            int r = q / 50, c = q - r * 50;
            int b = b0 + r; if (b >= B_) b = B_ - 1;
            const float* src = sent + (size_t)(b * S_ + t) * 200 + c * 4;
            CP_ASYNC16(st_addr + (uint32_t)(buf * 1400 + r * 200 + c * 4) * 4, src);
        }
        CP_COMMIT();
    };
    stage_st(0, 0);
    CP_WAIT0();
    __syncthreads();

    int cur = 0;
    for (int t = 0; t < S_; t++) {
        const float* st = st2b + cur * 1400;
        // convert st -> fp16 hi/lo tiles
        for (int i = tid; i < 1400; i += 256) {
            int r = i / 200, j = i - r * 200;
            float v = st[i];
            __half h = __float2half_rn(v);
            sthi[r * ST_PITCH + j] = h;
            stlo[r * ST_PITCH + j] = __float2half_rn(v - __half2float(h));
        }
        // prefetch next step's st
        if (t + 1 < S_) stage_st(t + 1, cur ^ 1);
        __syncthreads();

        // mma: P[gate][row] = Wnov . st  (3 passes: Whi*sthi + Whi*stlo + Wlo*sthi)
        float acc0[4] = {0.f, 0.f, 0.f, 0.f};
        float acc1[4] = {0.f, 0.f, 0.f, 0.f};
        for (int c = 0; c < NKCH; c++) {
            uint32_t hoff = hbase + (uint32_t)c * 32;
            uint32_t bhi[4], blo[4];
            ldm4(bhi, sthi_a + hoff);
            ldm4(blo, stlo_a + hoff);
            uint32_t cslot = (uint32_t)(c * WNCH_BYTES);
            if (v0) {
                uint32_t awh[4], awl[4];
                ldm4(awh, whi_a + cslot + aw0);
                ldm4(awl, wlo_a + cslot + aw0);
                mma_f16(acc0, awh, &bhi[0]);
                mma_f16(acc0, awh, &blo[0]);
                mma_f16(acc0, awl, &bhi[0]);
            }
            if (v1) {
                uint32_t awh[4], awl[4];
                ldm4(awh, whi_a + cslot + aw1);
                ldm4(awl, wlo_a + cslot + aw1);
                mma_f16(acc1, awh, &bhi[0]);
                mma_f16(acc1, awh, &blo[0]);
                mma_f16(acc1, awl, &bhi[0]);
            }
        }
        // epilogue: write P (no bias yet) transposed into ps[row][gate]
        {
            int col = (lane & 3) * 2;
            if (v0) {
                int gate = mt0 * 16 + (lane >> 2);
                ps[col * PS_PITCH + gate]           = acc0[0];
                ps[(col + 1) * PS_PITCH + gate]     = acc0[1];
                ps[col * PS_PITCH + gate + 8]       = acc0[2];
                ps[(col + 1) * PS_PITCH + gate + 8] = acc0[3];
            }
            if (v1) {
                int gate = mt1 * 16 + (lane >> 2);
                ps[col * PS_PITCH + gate]           = acc1[0];
                ps[(col + 1) * PS_PITCH + gate]     = acc1[1];
                ps[col * PS_PITCH + gate + 8]       = acc1[2];
                ps[(col + 1) * PS_PITCH + gate + 8] = acc1[3];
            }
        }
        __syncthreads();

        // reduce per batch row: content + salience - novelty + pos logits
        if (wrp < NOV_ROWS) {
            int b = b0 + wrp; if (b >= B_) b = B_ - 1;
            float acc = 0.f;
            for (int j = lane; j < 200; j += 32)
                acc += st[wrp * 200 + j] * wd[wrp * 200 + j]
                     - (ps[wrp * PS_PITCH + j] + bnv[j]) * tanhf(sum_s[wrp * 200 + j]);
            int ap = apos[b * S_ + t]; ap = ap < 0 ? 0 : (ap > 50 ? 50 : ap);
            int rp = rpos[b * S_ + t]; rp = rp < 0 ? 0 : (rp > 4 ? 4 : rp);
            for (int p = lane; p < 50; p += 32)
                acc += apos_table[ap * 50 + p] * apos_w[p] + rpos_table[rp * 50 + p] * rpos_w[p];
            for (int off = 16; off; off >>= 1) acc += __shfl_down_sync(0xffffffffu, acc, off);
            if (lane == 0) {
                float logit = acc + sm[9199];
                if (b0 + wrp < B_) out[(size_t)(b0 + wrp) * S_ + t] = logit;
                gsig[wrp] = 1.f / (1.f + __expf(-logit));
            }
        }
        __syncthreads();
        for (int i = tid; i < 1400; i += 256) {
            int r = i / 200;
            sum_s[i] += st[i] * gsig[r];
        }
        // wait next-step st before flipping (also keeps barrier count low)
        if (t + 1 < S_) CP_WAIT0();
        __syncthreads();
        cur ^= 1;
    }
}

// ---------------- host launch ----------------
static float* sym_addr(const void* sym) {
    void* p = nullptr;
    cudaGetSymbolAddress(&p, sym);
    return (float*)p;
}

extern "C" void kernel_launch(void* const* d_in, const int* in_sizes, int n_in,
                              void* d_out, int out_size) {
    const float* seq        = (const float*)d_in[0];
    const int*   apos       = (const int*)d_in[1];
    const int*   rpos       = (const int*)d_in[2];
    const int*   length     = (const int*)d_in[3];
    const float* apos_table = (const float*)d_in[4];
    const float* rpos_table = (const float*)d_in[5];
    const float* apos_w     = (const float*)d_in[6];
    const float* apos_b     = (const float*)d_in[7];
    const float* rpos_w     = (const float*)d_in[8];
    const float* rpos_b     = (const float*)d_in[9];
    const float* Wih_f      = (const float*)d_in[10];
    const float* Whh_f      = (const float*)d_in[11];
    const float* bih_f      = (const float*)d_in[12];
    const float* bhh_f      = (const float*)d_in[13];
    const float* Wih_b      = (const float*)d_in[14];
    const float* Whh_b      = (const float*)d_in[15];
    const float* bih_b      = (const float*)d_in[16];
    const float* bhh_b      = (const float*)d_in[17];
    const float* Wsent      = (const float*)d_in[18];
    const float* bsent      = (const float*)d_in[19];
    const float* wcont      = (const float*)d_in[20];
    const float* bcont      = (const float*)d_in[21];
    const float* Wdoc1      = (const float*)d_in[22];
    const float* bdoc1      = (const float*)d_in[23];
    const float* Wdoc2      = (const float*)d_in[24];
    const float* bdoc2      = (const float*)d_in[25];
    const float* Wnov       = (const float*)d_in[26];
    const float* bnov       = (const float*)d_in[27];
    const float* bias       = (const float*)d_in[28];
    float* out = (float*)d_out;

    float* gx     = sym_addr(g_gx);
    float* sent   = sym_addr(g_sent);
    float* avg    = sym_addr(g_avg);
    float* tmp    = sym_addr(g_tmp);
    float* doc    = sym_addr(g_doc);
    __half* Wc   = (__half*)sym_addr(g_Wc);
    __half* Wnhi = (__half*)sym_addr(g_Wnhi);
    __half* Wnlo = (__half*)sym_addr(g_Wnlo);
    __half* Ahi = (__half*)sym_addr(g_Ahi);
    __half* Alo = (__half*)sym_addr(g_Alo);
    __half* Hhi = (__half*)sym_addr(g_Hhi);
    __half* Hlo = (__half*)sym_addr(g_Hlo);
    __half* Bgx = (__half*)sym_addr(g_Bgx);
    __half* Bse = (__half*)sym_addr(g_Bse);

    cudaFuncSetAttribute(mma_gemm<0>, cudaFuncAttributeMaxDynamicSharedMemorySize, MMA_SMEM);
    cudaFuncSetAttribute(mma_gemm<1>, cudaFuncAttributeMaxDynamicSharedMemorySize, MMA_SMEM);
    cudaFuncSetAttribute(gru_kernel, cudaFuncAttributeMaxDynamicSharedMemorySize, GRU_SMEM);
    cudaFuncSetAttribute(nov_kernel, cudaFuncAttributeMaxDynamicSharedMemorySize, NOV_SMEM);

    // launch 1: weight packs (Whh fp16 chunks + Wnov hi/lo chunks)
    pack_all<<<(2 * NCHUNK * GATES * 16 + WN_TOTAL + 255) / 256, 256>>>(
        Whh_f, Whh_b, Wnov, Wc, Wnhi, Wnlo);
    // launch 2: gx-side conversions
    conv_prep<<<1600 + (int)(((size_t)M_ * KP_GX + 255) / 256), 256>>>(
        Wih_f, Wih_b, seq, Bgx, Ahi, Alo);
    // launch 3: combined gx GEMM
    mma_gemm<0><<<dim3(NP_GX / 128, M_ / 128), 256, MMA_SMEM>>>(
        Ahi, Alo, Bgx, bih_f, bih_b, 600, gx, NGX, NGX, KP_GX);
    // launch 4 (profiled): tensor-core GRU
    gru_kernel<<<dim3(74, 2), 608, GRU_SMEM>>>(
        gx, Wc, bhh_f, bhh_b, Hhi, Hlo);

    // sent-weight conversion + sent GEMM
    conv_f16<<<((size_t)NP_SENT * KP_SENT + 255) / 256, 256>>>(
        Wsent, 200, 2 * H_, KP_SENT, NP_SENT, Bse);
    mma_gemm<1><<<dim3(NP_SENT / 128, M_ / 128), 256, MMA_SMEM>>>(
        Hhi, Hlo, Bse, bsent, bsent, H_, sent, H_, H_, KP_SENT);

    // avg + doc MLP
    avg_kernel<<<(B_ * H_ + 255) / 256, 256>>>(sent, length, avg);
    sgemm_nt<2><<<dim3(2, 8), 256>>>(avg, Wdoc1, bdoc1, tmp, B_, H_, H_);
    sgemm_nt<0><<<dim3(2, 8), 256>>>(tmp, Wdoc2, bdoc2, doc, B_, H_, H_);

    // tensor-core novelty scan + fused base -> output
    nov_kernel<<<148, 256, NOV_SMEM>>>(sent, Wnhi, Wnlo, bnov, wcont, doc, apos, rpos,
                                       apos_table, rpos_table, apos_w, rpos_w,
                                       apos_b, rpos_b, bcont, bias, out);
}